// round 5
// baseline (speedup 1.0000x reference)
#include <cuda_runtime.h>
#include <cstdint>
#include <math.h>

#define NTOK 16384
#define DIM  1024
#define NE   8
#define CAP  2560          // int(1.25 * 16384 / 8)
#define BK   32
#define NCH  (DIM / BK)
#define PITCH 80           // bytes per SMEM tile row (32 bf16 = 64B + 16B pad)
#define TILE_B (128 * PITCH)          // 10240
#define STAGE_B (4 * TILE_B)          // 40960
#define SMEM_DYN (512 + 4 * STAGE_B)  // 164352

// ---------------- device scratch (no allocation allowed) -------------------
__device__ int      g_top[NTOK * 2];
__device__ float    g_gate[NTOK * 2];
__device__ int      g_slot[NTOK * 2];
__device__ int      g_row_token[NE * CAP];
__device__ int      g_load[NE];
__device__ uint16_t g_xh[(size_t)NTOK * DIM];          // x hi/lo bf16 (32MB ea)
__device__ uint16_t g_xl[(size_t)NTOK * DIM];
__device__ uint16_t g_w1h[(size_t)NE * DIM * DIM];     // W hi/lo bf16 (16MB ea)
__device__ uint16_t g_w1l[(size_t)NE * DIM * DIM];
__device__ uint16_t g_w2h[(size_t)NE * DIM * DIM];
__device__ uint16_t g_w2l[(size_t)NE * DIM * DIM];
__device__ uint16_t g_Hh[(size_t)NE * CAP * DIM];      // hidden hi/lo (40MB ea)
__device__ uint16_t g_Hl[(size_t)NE * CAP * DIM];
__device__ float    g_O[(size_t)NE * CAP * DIM];       // expert out + b2 (84MB)

// ---------------- helpers ---------------------------------------------------
__device__ __forceinline__ uint32_t smem_u32(const void* p) {
    uint32_t a;
    asm("{ .reg .u64 t; cvta.to.shared.u64 t, %1; cvt.u32.u64 %0, t; }"
        : "=r"(a) : "l"(p));
    return a;
}
__device__ __forceinline__ void cpa16(uint32_t dst, const void* src) {
    asm volatile("cp.async.cg.shared.global [%0], [%1], 16;"
                 :: "r"(dst), "l"(src));
}
#define CP_COMMIT() asm volatile("cp.async.commit_group;" ::: "memory")
#define CP_WAIT3()  asm volatile("cp.async.wait_group 3;" ::: "memory")

__device__ __forceinline__ void ldsm4(uint32_t* r, uint32_t addr) {
    asm volatile("ldmatrix.sync.aligned.m8n8.x4.shared.b16 {%0,%1,%2,%3}, [%4];"
                 : "=r"(r[0]), "=r"(r[1]), "=r"(r[2]), "=r"(r[3]) : "r"(addr));
}
__device__ __forceinline__ void mma_bf16(float* d, const uint32_t* a,
                                         const uint32_t* b) {
    asm volatile(
        "mma.sync.aligned.m16n8k16.row.col.f32.bf16.bf16.f32 "
        "{%0,%1,%2,%3}, {%4,%5,%6,%7}, {%8,%9}, {%0,%1,%2,%3};"
        : "+f"(d[0]), "+f"(d[1]), "+f"(d[2]), "+f"(d[3])
        : "r"(a[0]), "r"(a[1]), "r"(a[2]), "r"(a[3]), "r"(b[0]), "r"(b[1]));
}
// pack 2 fp32 -> bf16x2 hi + residual bf16x2 lo
__device__ __forceinline__ void split2(float a, float b, uint32_t& h, uint32_t& l) {
    asm("cvt.rn.bf16x2.f32 %0, %1, %2;" : "=r"(h) : "f"(b), "f"(a));
    float ra = a - __uint_as_float(h << 16);
    float rb = b - __uint_as_float(h & 0xFFFF0000u);
    asm("cvt.rn.bf16x2.f32 %0, %1, %2;" : "=r"(l) : "f"(rb), "f"(ra));
}

// ---------------- pre-split: fp32 -> bf16 hi/lo (memory-bound) -------------
__global__ void split_kernel(const float4* __restrict__ src,
                             uint2* __restrict__ hi, uint2* __restrict__ lo,
                             int n4) {
    int i = blockIdx.x * blockDim.x + threadIdx.x;
    if (i >= n4) return;
    float4 v = src[i];
    uint32_t h0, l0, h1, l1;
    split2(v.x, v.y, h0, l0);
    split2(v.z, v.w, h1, l1);
    hi[i] = make_uint2(h0, h1);
    lo[i] = make_uint2(l0, l1);
}

// ---------------- tensor-core (HMMA) GEMM, both layers ---------------------
// C[128x128] = A[128x1024] @ W[e][128x1024]^T  (+bias; relu+bf16 split for G1)
// 3-term bf16 split: Ah*Bh + Ah*Bl + Al*Bh, fp32 accumulate.
// Operands pre-split in global; cp.async 4-stage pipeline into SMEM.
template <bool G2>
__global__ void __launch_bounds__(256)
moe_gemm(const float* __restrict__ bias) {
    extern __shared__ __align__(16) char dsm[];
    int* rows = (int*)dsm;

    const int e = blockIdx.z;
    const int loadE = g_load[e];
    const int m0 = blockIdx.y * 128;
    if (m0 >= loadE) return;
    const int n0 = blockIdx.x * 128;
    const int tid = threadIdx.x;
    const int lane = tid & 31, wid = tid >> 5;
    const int wm = wid >> 2, wn = wid & 3;     // warp tile 64x32
    const uint32_t sb = smem_u32(dsm);

    if (!G2 && tid < 128) {
        int m = m0 + tid;
        rows[tid] = g_row_token[e * CAP + (m < loadE ? m : loadE - 1)];
    }
    __syncthreads();

    // cp.async assignment: thread -> row r, 32B half j of the 64B row chunk
    const int r = tid & 127;
    const int j = tid >> 7;
    size_t arow;
    if (G2) arow = ((size_t)e * CAP + m0 + r) * DIM;
    else    arow = (size_t)rows[r] * DIM;
    const size_t brow = ((size_t)e * DIM + n0 + r) * DIM;
    const uint16_t* pAh = (G2 ? g_Hh : g_xh) + arow + j * 16;
    const uint16_t* pAl = (G2 ? g_Hl : g_xl) + arow + j * 16;
    const uint16_t* pBh = (G2 ? g_w2h : g_w1h) + brow + j * 16;
    const uint16_t* pBl = (G2 ? g_w2l : g_w1l) + brow + j * 16;
    const uint32_t drow = sb + 512 + (uint32_t)r * PITCH + (uint32_t)j * 32;

    auto issue = [&](int c) {
        const uint32_t d = drow + (uint32_t)(c & 3) * STAGE_B;
        const uint16_t* sa_h = pAh + c * BK;
        const uint16_t* sa_l = pAl + c * BK;
        const uint16_t* sb_h = pBh + c * BK;
        const uint16_t* sb_l = pBl + c * BK;
        cpa16(d,                sa_h); cpa16(d + 16,                sa_h + 8);
        cpa16(d + TILE_B,       sa_l); cpa16(d + TILE_B + 16,       sa_l + 8);
        cpa16(d + 2 * TILE_B,   sb_h); cpa16(d + 2 * TILE_B + 16,   sb_h + 8);
        cpa16(d + 3 * TILE_B,   sb_l); cpa16(d + 3 * TILE_B + 16,   sb_l + 8);
    };

    // ldmatrix fragment addresses (reg + immediate thereafter)
    uint32_t aoff[4], boff[2];
#pragma unroll
    for (int ms = 0; ms < 4; ms++)
        aoff[ms] = (uint32_t)(wm * 64 + ms * 16 + (lane & 15)) * PITCH
                 + (uint32_t)(lane >> 4) * 16;
#pragma unroll
    for (int np = 0; np < 2; np++)
        boff[np] = (uint32_t)(wn * 32 + np * 16 + (lane & 7) + ((lane >> 4) & 1) * 8)
                 * PITCH + (uint32_t)((lane >> 3) & 1) * 16;

    float acc[4][4][4];
#pragma unroll
    for (int i = 0; i < 4; i++)
#pragma unroll
        for (int jj = 0; jj < 4; jj++)
#pragma unroll
            for (int k = 0; k < 4; k++) acc[i][jj][k] = 0.f;

    auto compute = [&](int st) {
        const uint32_t Ah = sb + 512 + (uint32_t)st * STAGE_B;
        const uint32_t Al = Ah + TILE_B;
        const uint32_t Bh = Ah + 2 * TILE_B;
        const uint32_t Bl = Ah + 3 * TILE_B;
#pragma unroll
        for (int s = 0; s < 2; s++) {
            uint32_t ah[4][4], al[4][4], bh[4][2], bl[4][2];
#pragma unroll
            for (int ms = 0; ms < 4; ms++) {
                ldsm4(ah[ms], Ah + aoff[ms] + s * 32);
                ldsm4(al[ms], Al + aoff[ms] + s * 32);
            }
#pragma unroll
            for (int np = 0; np < 2; np++) {
                uint32_t t[4];
                ldsm4(t, Bh + boff[np] + s * 32);
                bh[2 * np][0] = t[0]; bh[2 * np][1] = t[1];
                bh[2 * np + 1][0] = t[2]; bh[2 * np + 1][1] = t[3];
                ldsm4(t, Bl + boff[np] + s * 32);
                bl[2 * np][0] = t[0]; bl[2 * np][1] = t[1];
                bl[2 * np + 1][0] = t[2]; bl[2 * np + 1][1] = t[3];
            }
#pragma unroll
            for (int ms = 0; ms < 4; ms++)
#pragma unroll
                for (int ns = 0; ns < 4; ns++) {
                    mma_bf16(acc[ms][ns], ah[ms], bh[ns]);
                    mma_bf16(acc[ms][ns], ah[ms], bl[ns]);
                    mma_bf16(acc[ms][ns], al[ms], bh[ns]);
                }
        }
    };

    issue(0); CP_COMMIT();
    issue(1); CP_COMMIT();
    issue(2); CP_COMMIT();
#pragma unroll 1
    for (int c = 0; c < NCH; c++) {
        if (c + 3 < NCH) issue(c + 3);   // stage (c+3)&3 == (c-1)&3: freed last iter
        CP_COMMIT();
        CP_WAIT3();                       // group c complete
        __syncthreads();
        compute(c & 3);
        __syncthreads();                  // protect stage before rewrite
    }

    // epilogue
    const float* bE = bias + e * DIM;
#pragma unroll
    for (int ms = 0; ms < 4; ms++) {
        const int row = m0 + wm * 64 + ms * 16 + (lane >> 2);
#pragma unroll
        for (int ns = 0; ns < 4; ns++) {
            const int col = n0 + wn * 32 + ns * 8 + 2 * (lane & 3);
            const float2 bv = *(const float2*)(bE + col);
            float2 v0, v1;
            v0.x = acc[ms][ns][0] + bv.x; v0.y = acc[ms][ns][1] + bv.y;
            v1.x = acc[ms][ns][2] + bv.x; v1.y = acc[ms][ns][3] + bv.y;
            const size_t idx0 = ((size_t)e * CAP + row) * DIM + col;
            if (G2) {
                *(float2*)(g_O + idx0) = v0;
                *(float2*)(g_O + idx0 + 8 * DIM) = v1;
            } else {
                v0.x = v0.x > 0.f ? v0.x : 0.f; v0.y = v0.y > 0.f ? v0.y : 0.f;
                v1.x = v1.x > 0.f ? v1.x : 0.f; v1.y = v1.y > 0.f ? v1.y : 0.f;
                uint32_t h, l;
                split2(v0.x, v0.y, h, l);
                *(uint32_t*)(g_Hh + idx0) = h;
                *(uint32_t*)(g_Hl + idx0) = l;
                split2(v1.x, v1.y, h, l);
                *(uint32_t*)(g_Hh + idx0 + 8 * DIM) = h;
                *(uint32_t*)(g_Hl + idx0 + 8 * DIM) = l;
            }
        }
    }
}

// ---------------- router ---------------------------------------------------
__global__ void router_kernel(const float* __restrict__ x,
                              const float* __restrict__ Wr,
                              const float* __restrict__ br) {
    int token = (blockIdx.x * blockDim.x + threadIdx.x) >> 5;
    int lane  = threadIdx.x & 31;
    if (token >= NTOK) return;
    const float* xr = x + (size_t)token * DIM;
    float acc[NE];
#pragma unroll
    for (int e = 0; e < NE; e++) acc[e] = 0.f;
    for (int d = lane; d < DIM; d += 32) {
        float xv = xr[d];
#pragma unroll
        for (int e = 0; e < NE; e++) acc[e] += xv * Wr[e * DIM + d];
    }
#pragma unroll
    for (int e = 0; e < NE; e++)
#pragma unroll
        for (int o = 16; o; o >>= 1)
            acc[e] += __shfl_xor_sync(0xffffffffu, acc[e], o);
    if (lane == 0) {
        float l[NE];
#pragma unroll
        for (int e = 0; e < NE; e++) l[e] = acc[e] + br[e];
        float v1 = -3.4e38f; int i1 = 0;
#pragma unroll
        for (int e = 0; e < NE; e++) if (l[e] > v1) { v1 = l[e]; i1 = e; }
        float v2 = -3.4e38f; int i2 = 0;
#pragma unroll
        for (int e = 0; e < NE; e++) if (e != i1 && l[e] > v2) { v2 = l[e]; i2 = e; }
        float ex = expf(v2 - v1);
        float inv = 1.f / (1.f + ex);
        g_top[2 * token]      = i1;
        g_top[2 * token + 1]  = i2;
        g_gate[2 * token]     = inv;
        g_gate[2 * token + 1] = ex * inv;
    }
}

// ---------------- dispatch scan --------------------------------------------
__global__ void scan_kernel() {
    int e = blockIdx.x;
    __shared__ int wsum[32];
    __shared__ int total_s;
    int lane = threadIdx.x & 31;
    int wid  = threadIdx.x >> 5;
    int running = 0;
    for (int base = 0; base < NTOK; base += 1024) {
        int n = base + threadIdx.x;
        int k = -1;
        int t0 = g_top[2 * n], t1 = g_top[2 * n + 1];
        if (t0 == e) k = 0; else if (t1 == e) k = 1;
        unsigned b = __ballot_sync(0xffffffffu, k >= 0);
        int pw = __popc(b & ((1u << lane) - 1u));
        if (lane == 0) wsum[wid] = __popc(b);
        __syncthreads();
        if (wid == 0) {
            int v = wsum[lane];
            int s = v;
#pragma unroll
            for (int o = 1; o < 32; o <<= 1) {
                int u = __shfl_up_sync(0xffffffffu, s, o);
                if (lane >= o) s += u;
            }
            wsum[lane] = s - v;
            if (lane == 31) total_s = s;
        }
        __syncthreads();
        if (k >= 0) {
            int pos = running + wsum[wid] + pw;
            if (pos < CAP) {
                g_row_token[e * CAP + pos] = n;
                g_slot[2 * n + k] = pos;
            } else {
                g_slot[2 * n + k] = -1;
            }
        }
        running += total_s;
        __syncthreads();
    }
    if (threadIdx.x == 0) g_load[e] = running < CAP ? running : CAP;
}

// ---------------- combine: out[t] = sum_k gate * O[e_k, slot_k] ------------
__global__ void combine_kernel(float* __restrict__ out) {
    int t = blockIdx.x * 8 + (threadIdx.x >> 5);
    int lane = threadIdx.x & 31;
    float4 acc[8];
#pragma unroll
    for (int i = 0; i < 8; i++) acc[i] = make_float4(0.f, 0.f, 0.f, 0.f);
#pragma unroll
    for (int k = 0; k < 2; k++) {
        int s = g_slot[2 * t + k];
        if (s >= 0) {
            int e = g_top[2 * t + k];
            float g = g_gate[2 * t + k];
            const float4* p = (const float4*)(g_O + ((size_t)e * CAP + s) * DIM);
#pragma unroll
            for (int i = 0; i < 8; i++) {
                float4 v = __ldg(p + lane + i * 32);
                acc[i].x += g * v.x; acc[i].y += g * v.y;
                acc[i].z += g * v.z; acc[i].w += g * v.w;
            }
        }
    }
    float4* o = (float4*)(out + (size_t)t * DIM);
#pragma unroll
    for (int i = 0; i < 8; i++) o[lane + i * 32] = acc[i];
}

// ---------------- stats -----------------------------------------------------
__global__ void stats_kernel(float* __restrict__ out) {
    if (threadIdx.x == 0) {
        float l[NE], s = 0.f;
#pragma unroll
        for (int e = 0; e < NE; e++) { l[e] = (float)g_load[e]; s += l[e]; }
        float inv = 1.f / (s + 1e-8f);
        float loss = 0.f;
#pragma unroll
        for (int e = 0; e < NE; e++) {
            float d = l[e] * inv;
            out[(size_t)NTOK * DIM + 1 + e] = d;
            loss -= d * logf(d + 1e-8f);
        }
        out[(size_t)NTOK * DIM] = loss;
    }
}

// ---------------- launch ----------------------------------------------------
extern "C" void kernel_launch(void* const* d_in, const int* in_sizes, int n_in,
                              void* d_out, int out_size) {
    const float* x  = (const float*)d_in[0];
    const float* Wr = (const float*)d_in[1];
    const float* br = (const float*)d_in[2];
    const float* W1 = (const float*)d_in[3];
    const float* b1 = (const float*)d_in[4];
    const float* W2 = (const float*)d_in[5];
    const float* b2 = (const float*)d_in[6];
    float* out = (float*)d_out;

    cudaFuncSetAttribute(moe_gemm<false>,
                         cudaFuncAttributeMaxDynamicSharedMemorySize, SMEM_DYN);
    cudaFuncSetAttribute(moe_gemm<true>,
                         cudaFuncAttributeMaxDynamicSharedMemorySize, SMEM_DYN);

    uint16_t *xh, *xl, *w1h, *w1l, *w2h, *w2l;
    cudaGetSymbolAddress((void**)&xh,  g_xh);
    cudaGetSymbolAddress((void**)&xl,  g_xl);
    cudaGetSymbolAddress((void**)&w1h, g_w1h);
    cudaGetSymbolAddress((void**)&w1l, g_w1l);
    cudaGetSymbolAddress((void**)&w2h, g_w2h);
    cudaGetSymbolAddress((void**)&w2l, g_w2l);

    const int xn4 = NTOK * DIM / 4;
    const int wn4 = NE * DIM * DIM / 4;
    split_kernel<<<xn4 / 256, 256>>>((const float4*)x,  (uint2*)xh,  (uint2*)xl,  xn4);
    split_kernel<<<wn4 / 256, 256>>>((const float4*)W1, (uint2*)w1h, (uint2*)w1l, wn4);
    split_kernel<<<wn4 / 256, 256>>>((const float4*)W2, (uint2*)w2h, (uint2*)w2l, wn4);

    router_kernel<<<NTOK / 8, 256>>>(x, Wr, br);
    scan_kernel<<<NE, 1024>>>();
    dim3 grid(DIM / 128, CAP / 128, NE);
    moe_gemm<false><<<grid, 256, SMEM_DYN>>>(b1);
    moe_gemm<true><<<grid, 256, SMEM_DYN>>>(b2);
    combine_kernel<<<NTOK / 8, 256>>>(out);
    stats_kernel<<<1, 32>>>(out);
}

// round 6
// speedup vs baseline: 1.3254x; 1.3254x over previous
#include <cuda_runtime.h>
#include <cstdint>
#include <math.h>

#define NTOK 16384
#define DIM  1024
#define NE   8
#define CAP  2560          // int(1.25 * 16384 / 8)
#define BK   32
#define NCH  (DIM / BK)
#define PITCH 80
#define AL_OFF  20480      // 256*80
#define BH_OFF  40960
#define BL_OFF  51200
#define STAGE_B 61440
#define SMEM_DYN (1024 + 3 * STAGE_B)   // 185344

// ---------------- device scratch (no allocation allowed) -------------------
__device__ int      g_top[NTOK * 2];
__device__ float    g_gate[NTOK * 2];
__device__ int      g_slot[NTOK * 2];
__device__ int      g_row_token[NE * CAP];
__device__ int      g_load[NE];
__device__ uint16_t g_xh[(size_t)NTOK * DIM];
__device__ uint16_t g_xl[(size_t)NTOK * DIM];
__device__ uint16_t g_w1h[(size_t)NE * DIM * DIM];
__device__ uint16_t g_w1l[(size_t)NE * DIM * DIM];
__device__ uint16_t g_w2h[(size_t)NE * DIM * DIM];
__device__ uint16_t g_w2l[(size_t)NE * DIM * DIM];
__device__ uint16_t g_Hh[(size_t)NE * CAP * DIM];
__device__ uint16_t g_Hl[(size_t)NE * CAP * DIM];
__device__ float    g_O[(size_t)NE * CAP * DIM];

// ---------------- helpers ---------------------------------------------------
__device__ __forceinline__ uint32_t smem_u32(const void* p) {
    uint32_t a;
    asm("{ .reg .u64 t; cvta.to.shared.u64 t, %1; cvt.u32.u64 %0, t; }"
        : "=r"(a) : "l"(p));
    return a;
}
__device__ __forceinline__ void cpa16(uint32_t dst, const void* src) {
    asm volatile("cp.async.cg.shared.global [%0], [%1], 16;"
                 :: "r"(dst), "l"(src));
}
#define CP_COMMIT() asm volatile("cp.async.commit_group;" ::: "memory")
#define CP_WAIT2()  asm volatile("cp.async.wait_group 2;" ::: "memory")

__device__ __forceinline__ void ldsm4(uint32_t* r, uint32_t addr) {
    asm volatile("ldmatrix.sync.aligned.m8n8.x4.shared.b16 {%0,%1,%2,%3}, [%4];"
                 : "=r"(r[0]), "=r"(r[1]), "=r"(r[2]), "=r"(r[3]) : "r"(addr));
}
__device__ __forceinline__ void mma_bf16(float* d, const uint32_t* a,
                                         const uint32_t* b) {
    asm volatile(
        "mma.sync.aligned.m16n8k16.row.col.f32.bf16.bf16.f32 "
        "{%0,%1,%2,%3}, {%4,%5,%6,%7}, {%8,%9}, {%0,%1,%2,%3};"
        : "+f"(d[0]), "+f"(d[1]), "+f"(d[2]), "+f"(d[3])
        : "r"(a[0]), "r"(a[1]), "r"(a[2]), "r"(a[3]), "r"(b[0]), "r"(b[1]));
}
__device__ __forceinline__ void split2(float a, float b, uint32_t& h, uint32_t& l) {
    asm("cvt.rn.bf16x2.f32 %0, %1, %2;" : "=r"(h) : "f"(b), "f"(a));
    float ra = a - __uint_as_float(h << 16);
    float rb = b - __uint_as_float(h & 0xFFFF0000u);
    asm("cvt.rn.bf16x2.f32 %0, %1, %2;" : "=r"(l) : "f"(rb), "f"(ra));
}

// ---------------- pre-split: fp32 -> bf16 hi/lo (memory-bound) -------------
__global__ void split_kernel(const float4* __restrict__ src,
                             uint2* __restrict__ hi, uint2* __restrict__ lo,
                             int n4) {
    int i = blockIdx.x * blockDim.x + threadIdx.x;
    if (i >= n4) return;
    float4 v = src[i];
    uint32_t h0, l0, h1, l1;
    split2(v.x, v.y, h0, l0);
    split2(v.z, v.w, h1, l1);
    hi[i] = make_uint2(h0, h1);
    lo[i] = make_uint2(l0, l1);
}

// ---------------- tensor-core (HMMA) GEMM, both layers ---------------------
// C[256x128] = A[256x1024] @ W[e][128x1024]^T  (+bias; relu+split for G1)
// 3-term bf16 split: Ah*Bh + Ah*Bl + Al*Bh, fp32 accumulate.
// All operands pre-split bf16 in global; cp.async 3-stage pipeline.
template <bool G2>
__global__ void __launch_bounds__(256)
moe_gemm(const float* __restrict__ bias) {
    extern __shared__ __align__(16) char dsm[];
    int* rows = (int*)dsm;

    const int e = blockIdx.z;
    const int loadE = g_load[e];
    const int m0 = blockIdx.y * 256;
    if (m0 >= loadE) return;
    const int n0 = blockIdx.x * 128;
    const int tid = threadIdx.x;
    const int lane = tid & 31, wid = tid >> 5;
    const int wm = wid >> 1, wn = wid & 1;     // warp tile 64x64
    const uint32_t sb = smem_u32(dsm);

    if (!G2) {
        int m = m0 + tid;
        rows[tid] = g_row_token[e * CAP + (m < loadE ? m : loadE - 1)];
    }
    __syncthreads();

    // ---- cp.async mapping: lane = (rl 0..7) x (q 0..3 16B chunk) ----
    const int q  = lane & 3;
    const int rl = lane >> 2;
    const uint16_t* pAh[4];
    uint32_t dA[4];
#pragma unroll
    for (int p = 0; p < 4; p++) {
        const int row = wid * 8 + rl + p * 64;
        size_t base = G2 ? ((size_t)e * CAP + m0 + row) * DIM
                         : (size_t)rows[row] * DIM;
        pAh[p] = (G2 ? g_Hh : g_xh) + base + q * 8;
        dA[p] = (uint32_t)row * PITCH + (uint32_t)q * 16;
    }
    const int browi = wid * 8 + rl;
    const uint16_t* pB0 = (G2 ? g_w2h : g_w1h)
                        + ((size_t)e * DIM + n0 + browi) * DIM + q * 8;
    const uint32_t dB0 = BH_OFF + (uint32_t)browi * PITCH + (uint32_t)q * 16;
    const ptrdiff_t dAl = (G2 ? (g_Hl - g_Hh) : (g_xl - g_xh));
    const ptrdiff_t dBl = (G2 ? (g_w2l - g_w2h) : (g_w1l - g_w1h));

    auto issue = [&](int c, uint32_t st) {
        const int k0 = c * BK;
#pragma unroll
        for (int p = 0; p < 4; p++) {
            const uint16_t* s = pAh[p] + k0;
            cpa16(st + dA[p], s);
            cpa16(st + dA[p] + AL_OFF, s + dAl);
        }
#pragma unroll
        for (int p = 0; p < 2; p++) {
            const uint16_t* s = pB0 + (size_t)p * 64 * DIM + k0;
            cpa16(st + dB0 + p * (64 * PITCH), s);
            cpa16(st + dB0 + p * (64 * PITCH) + (BL_OFF - BH_OFF), s + dBl);
        }
    };

    // ---- ldmatrix fragment offsets (stage-relative) ----
    uint32_t aoff[4], boff[4];
#pragma unroll
    for (int ms = 0; ms < 4; ms++)
        aoff[ms] = (uint32_t)(wm * 64 + ms * 16 + (lane & 15)) * PITCH
                 + (uint32_t)(lane >> 4) * 16;
#pragma unroll
    for (int np = 0; np < 4; np++)
        boff[np] = BH_OFF
                 + (uint32_t)(wn * 64 + np * 16 + (lane & 7) + ((lane >> 4) & 1) * 8)
                 * PITCH + (uint32_t)((lane >> 3) & 1) * 16;

    float acc[4][8][4];
#pragma unroll
    for (int i = 0; i < 4; i++)
#pragma unroll
        for (int j = 0; j < 8; j++)
#pragma unroll
            for (int k = 0; k < 4; k++) acc[i][j][k] = 0.f;

    auto compute = [&](uint32_t st) {
#pragma unroll
        for (int s = 0; s < 2; s++) {
            uint32_t ah[4][4], al[4][4], bh[8][2], bl[8][2];
#pragma unroll
            for (int ms = 0; ms < 4; ms++) {
                ldsm4(ah[ms], st + aoff[ms] + s * 32);
                ldsm4(al[ms], st + aoff[ms] + AL_OFF + s * 32);
            }
#pragma unroll
            for (int np = 0; np < 4; np++) {
                uint32_t t[4];
                ldsm4(t, st + boff[np] + s * 32);
                bh[2 * np][0] = t[0]; bh[2 * np][1] = t[1];
                bh[2 * np + 1][0] = t[2]; bh[2 * np + 1][1] = t[3];
                ldsm4(t, st + boff[np] + (BL_OFF - BH_OFF) + s * 32);
                bl[2 * np][0] = t[0]; bl[2 * np][1] = t[1];
                bl[2 * np + 1][0] = t[2]; bl[2 * np + 1][1] = t[3];
            }
#pragma unroll
            for (int ms = 0; ms < 4; ms++)
#pragma unroll
                for (int ns = 0; ns < 8; ns++) {
                    mma_bf16(acc[ms][ns], ah[ms], bh[ns]);
                    mma_bf16(acc[ms][ns], ah[ms], bl[ns]);
                    mma_bf16(acc[ms][ns], al[ms], bh[ns]);
                }
        }
    };

    const uint32_t st0 = sb + 1024;
    issue(0, st0);              CP_COMMIT();
    issue(1, st0 + STAGE_B);    CP_COMMIT();
    issue(2, st0 + 2 * STAGE_B); CP_COMMIT();

    int stg = 0;
#pragma unroll 1
    for (int c = 0; c < NCH; c++) {
        CP_WAIT2();
        __syncthreads();
        const uint32_t st = st0 + (uint32_t)stg * STAGE_B;
        compute(st);
        __syncthreads();
        if (c + 3 < NCH) issue(c + 3, st);
        CP_COMMIT();                       // always commit (empty group ok)
        stg = (stg == 2) ? 0 : stg + 1;
    }

    // ---- epilogue ----
    const float* bE = bias + e * DIM;
#pragma unroll
    for (int ms = 0; ms < 4; ms++) {
        const int row = m0 + wm * 64 + ms * 16 + (lane >> 2);
#pragma unroll
        for (int ns = 0; ns < 8; ns++) {
            const int col = n0 + wn * 64 + ns * 8 + 2 * (lane & 3);
            const float2 bv = *(const float2*)(bE + col);
            float2 v0, v1;
            v0.x = acc[ms][ns][0] + bv.x; v0.y = acc[ms][ns][1] + bv.y;
            v1.x = acc[ms][ns][2] + bv.x; v1.y = acc[ms][ns][3] + bv.y;
            const size_t idx0 = ((size_t)e * CAP + row) * DIM + col;
            if (G2) {
                *(float2*)(g_O + idx0) = v0;
                *(float2*)(g_O + idx0 + 8 * DIM) = v1;
            } else {
                v0.x = v0.x > 0.f ? v0.x : 0.f; v0.y = v0.y > 0.f ? v0.y : 0.f;
                v1.x = v1.x > 0.f ? v1.x : 0.f; v1.y = v1.y > 0.f ? v1.y : 0.f;
                uint32_t h, l;
                split2(v0.x, v0.y, h, l);
                *(uint32_t*)(g_Hh + idx0) = h;
                *(uint32_t*)(g_Hl + idx0) = l;
                split2(v1.x, v1.y, h, l);
                *(uint32_t*)(g_Hh + idx0 + 8 * DIM) = h;
                *(uint32_t*)(g_Hl + idx0 + 8 * DIM) = l;
            }
        }
    }
}

// ---------------- router ---------------------------------------------------
__global__ void router_kernel(const float* __restrict__ x,
                              const float* __restrict__ Wr,
                              const float* __restrict__ br) {
    int token = (blockIdx.x * blockDim.x + threadIdx.x) >> 5;
    int lane  = threadIdx.x & 31;
    if (token >= NTOK) return;
    const float* xr = x + (size_t)token * DIM;
    float acc[NE];
#pragma unroll
    for (int e = 0; e < NE; e++) acc[e] = 0.f;
    for (int d = lane; d < DIM; d += 32) {
        float xv = xr[d];
#pragma unroll
        for (int e = 0; e < NE; e++) acc[e] += xv * Wr[e * DIM + d];
    }
#pragma unroll
    for (int e = 0; e < NE; e++)
#pragma unroll
        for (int o = 16; o; o >>= 1)
            acc[e] += __shfl_xor_sync(0xffffffffu, acc[e], o);
    if (lane == 0) {
        float l[NE];
#pragma unroll
        for (int e = 0; e < NE; e++) l[e] = acc[e] + br[e];
        float v1 = -3.4e38f; int i1 = 0;
#pragma unroll
        for (int e = 0; e < NE; e++) if (l[e] > v1) { v1 = l[e]; i1 = e; }
        float v2 = -3.4e38f; int i2 = 0;
#pragma unroll
        for (int e = 0; e < NE; e++) if (e != i1 && l[e] > v2) { v2 = l[e]; i2 = e; }
        float ex = expf(v2 - v1);
        float inv = 1.f / (1.f + ex);
        g_top[2 * token]      = i1;
        g_top[2 * token + 1]  = i2;
        g_gate[2 * token]     = inv;
        g_gate[2 * token + 1] = ex * inv;
    }
}

// ---------------- dispatch scan --------------------------------------------
__global__ void scan_kernel() {
    int e = blockIdx.x;
    __shared__ int wsum[32];
    __shared__ int total_s;
    int lane = threadIdx.x & 31;
    int wid  = threadIdx.x >> 5;
    int running = 0;
    for (int base = 0; base < NTOK; base += 1024) {
        int n = base + threadIdx.x;
        int k = -1;
        int t0 = g_top[2 * n], t1 = g_top[2 * n + 1];
        if (t0 == e) k = 0; else if (t1 == e) k = 1;
        unsigned b = __ballot_sync(0xffffffffu, k >= 0);
        int pw = __popc(b & ((1u << lane) - 1u));
        if (lane == 0) wsum[wid] = __popc(b);
        __syncthreads();
        if (wid == 0) {
            int v = wsum[lane];
            int s = v;
#pragma unroll
            for (int o = 1; o < 32; o <<= 1) {
                int u = __shfl_up_sync(0xffffffffu, s, o);
                if (lane >= o) s += u;
            }
            wsum[lane] = s - v;
            if (lane == 31) total_s = s;
        }
        __syncthreads();
        if (k >= 0) {
            int pos = running + wsum[wid] + pw;
            if (pos < CAP) {
                g_row_token[e * CAP + pos] = n;
                g_slot[2 * n + k] = pos;
            } else {
                g_slot[2 * n + k] = -1;
            }
        }
        running += total_s;
        __syncthreads();
    }
    if (threadIdx.x == 0) g_load[e] = running < CAP ? running : CAP;
}

// ---------------- combine: out[t] = sum_k gate * O[e_k, slot_k] ------------
__global__ void combine_kernel(float* __restrict__ out) {
    int t = blockIdx.x * 8 + (threadIdx.x >> 5);
    int lane = threadIdx.x & 31;
    float4 acc[8];
#pragma unroll
    for (int i = 0; i < 8; i++) acc[i] = make_float4(0.f, 0.f, 0.f, 0.f);
#pragma unroll
    for (int k = 0; k < 2; k++) {
        int s = g_slot[2 * t + k];
        if (s >= 0) {
            int e = g_top[2 * t + k];
            float g = g_gate[2 * t + k];
            const float4* p = (const float4*)(g_O + ((size_t)e * CAP + s) * DIM);
#pragma unroll
            for (int i = 0; i < 8; i++) {
                float4 v = __ldg(p + lane + i * 32);
                acc[i].x += g * v.x; acc[i].y += g * v.y;
                acc[i].z += g * v.z; acc[i].w += g * v.w;
            }
        }
    }
    float4* o = (float4*)(out + (size_t)t * DIM);
#pragma unroll
    for (int i = 0; i < 8; i++) o[lane + i * 32] = acc[i];
}

// ---------------- stats -----------------------------------------------------
__global__ void stats_kernel(float* __restrict__ out) {
    if (threadIdx.x == 0) {
        float l[NE], s = 0.f;
#pragma unroll
        for (int e = 0; e < NE; e++) { l[e] = (float)g_load[e]; s += l[e]; }
        float inv = 1.f / (s + 1e-8f);
        float loss = 0.f;
#pragma unroll
        for (int e = 0; e < NE; e++) {
            float d = l[e] * inv;
            out[(size_t)NTOK * DIM + 1 + e] = d;
            loss -= d * logf(d + 1e-8f);
        }
        out[(size_t)NTOK * DIM] = loss;
    }
}

// ---------------- launch ----------------------------------------------------
extern "C" void kernel_launch(void* const* d_in, const int* in_sizes, int n_in,
                              void* d_out, int out_size) {
    const float* x  = (const float*)d_in[0];
    const float* Wr = (const float*)d_in[1];
    const float* br = (const float*)d_in[2];
    const float* W1 = (const float*)d_in[3];
    const float* b1 = (const float*)d_in[4];
    const float* W2 = (const float*)d_in[5];
    const float* b2 = (const float*)d_in[6];
    float* out = (float*)d_out;

    cudaFuncSetAttribute(moe_gemm<false>,
                         cudaFuncAttributeMaxDynamicSharedMemorySize, SMEM_DYN);
    cudaFuncSetAttribute(moe_gemm<true>,
                         cudaFuncAttributeMaxDynamicSharedMemorySize, SMEM_DYN);

    uint16_t *xh, *xl, *w1h, *w1l, *w2h, *w2l;
    cudaGetSymbolAddress((void**)&xh,  g_xh);
    cudaGetSymbolAddress((void**)&xl,  g_xl);
    cudaGetSymbolAddress((void**)&w1h, g_w1h);
    cudaGetSymbolAddress((void**)&w1l, g_w1l);
    cudaGetSymbolAddress((void**)&w2h, g_w2h);
    cudaGetSymbolAddress((void**)&w2l, g_w2l);

    const int xn4 = NTOK * DIM / 4;
    const int wn4 = NE * DIM * DIM / 4;
    split_kernel<<<xn4 / 256, 256>>>((const float4*)x,  (uint2*)xh,  (uint2*)xl,  xn4);
    split_kernel<<<wn4 / 256, 256>>>((const float4*)W1, (uint2*)w1h, (uint2*)w1l, wn4);
    split_kernel<<<wn4 / 256, 256>>>((const float4*)W2, (uint2*)w2h, (uint2*)w2l, wn4);

    router_kernel<<<NTOK / 8, 256>>>(x, Wr, br);
    scan_kernel<<<NE, 1024>>>();
    dim3 grid(DIM / 128, CAP / 256, NE);
    moe_gemm<false><<<grid, 256, SMEM_DYN>>>(b1);
    moe_gemm<true><<<grid, 256, SMEM_DYN>>>(b2);
    combine_kernel<<<NTOK / 8, 256>>>(out);
    stats_kernel<<<1, 32>>>(out);
}

// round 7
// speedup vs baseline: 1.5279x; 1.1528x over previous
#include <cuda_runtime.h>
#include <cuda_fp16.h>
#include <cstdint>
#include <math.h>

#define NTOK 16384
#define DIM  1024
#define NE   8
#define CAP  2560          // int(1.25 * 16384 / 8)
#define BK   32
#define NCH  (DIM / BK)
#define PITCH 80
#define BH_OFF  20480      // 256*80
#define BL_OFF  30720
#define STAGE_B 40960
#define SMEM_DYN (1024 + 3 * STAGE_B)   // 123904

// ---------------- device scratch (no allocation allowed) -------------------
__device__ int      g_top[NTOK * 2];
__device__ float    g_gate[NTOK * 2];
__device__ int      g_slot[NTOK * 2];
__device__ int      g_row_token[NE * CAP];
__device__ int      g_load[NE];
__device__ uint16_t g_xh[(size_t)NTOK * DIM];          // x as fp16
__device__ uint16_t g_w1h[(size_t)NE * DIM * DIM];     // W fp16 hi/lo
__device__ uint16_t g_w1l[(size_t)NE * DIM * DIM];
__device__ uint16_t g_w2h[(size_t)NE * DIM * DIM];
__device__ uint16_t g_w2l[(size_t)NE * DIM * DIM];
__device__ uint16_t g_Hh[(size_t)NE * CAP * DIM];      // hidden as fp16
__device__ float    g_O[(size_t)NE * CAP * DIM];       // expert out + b2

// ---------------- helpers ---------------------------------------------------
__device__ __forceinline__ uint32_t smem_u32(const void* p) {
    uint32_t a;
    asm("{ .reg .u64 t; cvta.to.shared.u64 t, %1; cvt.u32.u64 %0, t; }"
        : "=r"(a) : "l"(p));
    return a;
}
__device__ __forceinline__ void cpa16(uint32_t dst, const void* src) {
    asm volatile("cp.async.cg.shared.global [%0], [%1], 16;"
                 :: "r"(dst), "l"(src));
}
#define CP_COMMIT() asm volatile("cp.async.commit_group;" ::: "memory")
#define CP_WAIT2()  asm volatile("cp.async.wait_group 2;" ::: "memory")

__device__ __forceinline__ void ldsm4(uint32_t* r, uint32_t addr) {
    asm volatile("ldmatrix.sync.aligned.m8n8.x4.shared.b16 {%0,%1,%2,%3}, [%4];"
                 : "=r"(r[0]), "=r"(r[1]), "=r"(r[2]), "=r"(r[3]) : "r"(addr));
}
__device__ __forceinline__ void mma_f16(float* d, const uint32_t* a,
                                        const uint32_t* b) {
    asm volatile(
        "mma.sync.aligned.m16n8k16.row.col.f32.f16.f16.f32 "
        "{%0,%1,%2,%3}, {%4,%5,%6,%7}, {%8,%9}, {%0,%1,%2,%3};"
        : "+f"(d[0]), "+f"(d[1]), "+f"(d[2]), "+f"(d[3])
        : "r"(a[0]), "r"(a[1]), "r"(a[2]), "r"(a[3]), "r"(b[0]), "r"(b[1]));
}
__device__ __forceinline__ uint32_t cvt2h(float a, float b) {
    __half2 h = __floats2half2_rn(a, b);
    return *(uint32_t*)&h;
}
__device__ __forceinline__ void split2h(float a, float b,
                                        uint32_t& h, uint32_t& l) {
    __half2 hh = __floats2half2_rn(a, b);
    float2 bk = __half22float2(hh);
    __half2 ll = __floats2half2_rn(a - bk.x, b - bk.y);
    h = *(uint32_t*)&hh;
    l = *(uint32_t*)&ll;
}

// ---------------- W split: fp32 -> fp16 hi/lo ------------------------------
__global__ void splitw_kernel(const float4* __restrict__ src,
                              uint2* __restrict__ hi, uint2* __restrict__ lo,
                              int n4) {
    int i = blockIdx.x * blockDim.x + threadIdx.x;
    if (i >= n4) return;
    float4 v = src[i];
    uint32_t h0, l0, h1, l1;
    split2h(v.x, v.y, h0, l0);
    split2h(v.z, v.w, h1, l1);
    hi[i] = make_uint2(h0, h1);
    lo[i] = make_uint2(l0, l1);
}

// ---------------- router + x->fp16 conversion (fused; x read once) ---------
__global__ void router_kernel(const float* __restrict__ x,
                              const float* __restrict__ Wr,
                              const float* __restrict__ br) {
    int token = (blockIdx.x * blockDim.x + threadIdx.x) >> 5;
    int lane  = threadIdx.x & 31;
    if (token >= NTOK) return;
    const float4* xr = (const float4*)(x + (size_t)token * DIM);
    uint2* xo = (uint2*)(g_xh + (size_t)token * DIM);
    float acc[NE];
#pragma unroll
    for (int e = 0; e < NE; e++) acc[e] = 0.f;
#pragma unroll
    for (int i = 0; i < 8; i++) {
        const int d4 = lane + i * 32;
        float4 v = __ldg(xr + d4);
        xo[d4] = make_uint2(cvt2h(v.x, v.y), cvt2h(v.z, v.w));
#pragma unroll
        for (int e = 0; e < NE; e++) {
            const float4 w = __ldg((const float4*)(Wr + e * DIM) + d4);
            acc[e] += v.x * w.x + v.y * w.y + v.z * w.z + v.w * w.w;
        }
    }
#pragma unroll
    for (int e = 0; e < NE; e++)
#pragma unroll
        for (int o = 16; o; o >>= 1)
            acc[e] += __shfl_xor_sync(0xffffffffu, acc[e], o);
    if (lane == 0) {
        float l[NE];
#pragma unroll
        for (int e = 0; e < NE; e++) l[e] = acc[e] + br[e];
        float v1 = -3.4e38f; int i1 = 0;
#pragma unroll
        for (int e = 0; e < NE; e++) if (l[e] > v1) { v1 = l[e]; i1 = e; }
        float v2 = -3.4e38f; int i2 = 0;
#pragma unroll
        for (int e = 0; e < NE; e++) if (e != i1 && l[e] > v2) { v2 = l[e]; i2 = e; }
        float ex = expf(v2 - v1);
        float inv = 1.f / (1.f + ex);
        g_top[2 * token]      = i1;
        g_top[2 * token + 1]  = i2;
        g_gate[2 * token]     = inv;
        g_gate[2 * token + 1] = ex * inv;
    }
}

// ---------------- tensor-core (HMMA fp16) GEMM, both layers ----------------
// C[256x128] = A[256x1024] @ W[e][128x1024]^T  (+bias; relu+cvt for G1)
// 2-term fp16 split: A*Wh + A*Wl, fp32 accumulate.
template <bool G2>
__global__ void __launch_bounds__(256)
moe_gemm(const float* __restrict__ bias) {
    extern __shared__ __align__(16) char dsm[];
    int* rows = (int*)dsm;

    const int e = blockIdx.z;
    const int loadE = g_load[e];
    const int m0 = blockIdx.y * 256;
    if (m0 >= loadE) return;
    const int n0 = blockIdx.x * 128;
    const int tid = threadIdx.x;
    const int lane = tid & 31, wid = tid >> 5;
    const int wm = wid >> 1, wn = wid & 1;     // warp tile 64x64
    const uint32_t sb = smem_u32(dsm);

    if (!G2) {
        int m = m0 + tid;
        rows[tid] = g_row_token[e * CAP + (m < loadE ? m : loadE - 1)];
    }
    __syncthreads();

    // cp.async mapping: thread tid -> A row tid (4x16B); B row tid&127 of hi
    // (tid<128) or lo (tid>=128) buffer (4x16B)
    size_t abase = G2 ? ((size_t)e * CAP + m0 + tid) * DIM
                      : (size_t)rows[tid] * DIM;
    const uint16_t* pA = (G2 ? g_Hh : g_xh) + abase;
    const uint32_t dA = (uint32_t)tid * PITCH;
    const uint16_t* wsrc = G2 ? (tid < 128 ? g_w2h : g_w2l)
                              : (tid < 128 ? g_w1h : g_w1l);
    const uint16_t* pB = wsrc + ((size_t)e * DIM + n0 + (tid & 127)) * DIM;
    const uint32_t dB = BH_OFF + (uint32_t)(tid >> 7) * (BL_OFF - BH_OFF)
                      + (uint32_t)(tid & 127) * PITCH;

    auto issue = [&](int c, uint32_t st) {
        const int k0 = c * BK;
        const uint16_t* sa = pA + k0;
        const uint16_t* sbp = pB + k0;
#pragma unroll
        for (int q = 0; q < 4; q++) {
            cpa16(st + dA + q * 16, sa + q * 8);
            cpa16(st + dB + q * 16, sbp + q * 8);
        }
    };

    // ldmatrix fragment offsets (stage-relative)
    uint32_t aoff[4], boff[4];
#pragma unroll
    for (int ms = 0; ms < 4; ms++)
        aoff[ms] = (uint32_t)(wm * 64 + ms * 16 + (lane & 15)) * PITCH
                 + (uint32_t)(lane >> 4) * 16;
#pragma unroll
    for (int np = 0; np < 4; np++)
        boff[np] = BH_OFF
                 + (uint32_t)(wn * 64 + np * 16 + (lane & 7) + ((lane >> 4) & 1) * 8)
                 * PITCH + (uint32_t)((lane >> 3) & 1) * 16;

    float acc[4][8][4];
#pragma unroll
    for (int i = 0; i < 4; i++)
#pragma unroll
        for (int j = 0; j < 8; j++)
#pragma unroll
            for (int k = 0; k < 4; k++) acc[i][j][k] = 0.f;

    auto compute = [&](uint32_t st) {
#pragma unroll
        for (int s = 0; s < 2; s++) {
            uint32_t ah[4][4], bh[8][2], bl[8][2];
#pragma unroll
            for (int ms = 0; ms < 4; ms++)
                ldsm4(ah[ms], st + aoff[ms] + s * 32);
#pragma unroll
            for (int np = 0; np < 4; np++) {
                uint32_t t[4];
                ldsm4(t, st + boff[np] + s * 32);
                bh[2 * np][0] = t[0]; bh[2 * np][1] = t[1];
                bh[2 * np + 1][0] = t[2]; bh[2 * np + 1][1] = t[3];
                ldsm4(t, st + boff[np] + (BL_OFF - BH_OFF) + s * 32);
                bl[2 * np][0] = t[0]; bl[2 * np][1] = t[1];
                bl[2 * np + 1][0] = t[2]; bl[2 * np + 1][1] = t[3];
            }
#pragma unroll
            for (int ms = 0; ms < 4; ms++)
#pragma unroll
                for (int ns = 0; ns < 8; ns++) {
                    mma_f16(acc[ms][ns], ah[ms], bh[ns]);
                    mma_f16(acc[ms][ns], ah[ms], bl[ns]);
                }
        }
    };

    const uint32_t st0 = sb + 1024;
    issue(0, st0);               CP_COMMIT();
    issue(1, st0 + STAGE_B);     CP_COMMIT();
    issue(2, st0 + 2 * STAGE_B); CP_COMMIT();

    int stg = 0;
#pragma unroll 1
    for (int c = 0; c < NCH; c++) {
        CP_WAIT2();
        __syncthreads();
        const uint32_t st = st0 + (uint32_t)stg * STAGE_B;
        compute(st);
        __syncthreads();
        if (c + 3 < NCH) issue(c + 3, st);
        CP_COMMIT();                       // always commit (empty group ok)
        stg = (stg == 2) ? 0 : stg + 1;
    }

    // ---- epilogue ----
    const float* bE = bias + e * DIM;
#pragma unroll
    for (int ms = 0; ms < 4; ms++) {
        const int row = m0 + wm * 64 + ms * 16 + (lane >> 2);
#pragma unroll
        for (int ns = 0; ns < 8; ns++) {
            const int col = n0 + wn * 64 + ns * 8 + 2 * (lane & 3);
            const float2 bv = *(const float2*)(bE + col);
            float2 v0, v1;
            v0.x = acc[ms][ns][0] + bv.x; v0.y = acc[ms][ns][1] + bv.y;
            v1.x = acc[ms][ns][2] + bv.x; v1.y = acc[ms][ns][3] + bv.y;
            const size_t idx0 = ((size_t)e * CAP + row) * DIM + col;
            if (G2) {
                *(float2*)(g_O + idx0) = v0;
                *(float2*)(g_O + idx0 + 8 * DIM) = v1;
            } else {
                v0.x = v0.x > 0.f ? v0.x : 0.f; v0.y = v0.y > 0.f ? v0.y : 0.f;
                v1.x = v1.x > 0.f ? v1.x : 0.f; v1.y = v1.y > 0.f ? v1.y : 0.f;
                *(uint32_t*)(g_Hh + idx0) = cvt2h(v0.x, v0.y);
                *(uint32_t*)(g_Hh + idx0 + 8 * DIM) = cvt2h(v1.x, v1.y);
            }
        }
    }
}

// ---------------- dispatch scan --------------------------------------------
__global__ void scan_kernel() {
    int e = blockIdx.x;
    __shared__ int wsum[32];
    __shared__ int total_s;
    int lane = threadIdx.x & 31;
    int wid  = threadIdx.x >> 5;
    int running = 0;
    for (int base = 0; base < NTOK; base += 1024) {
        int n = base + threadIdx.x;
        int k = -1;
        int t0 = g_top[2 * n], t1 = g_top[2 * n + 1];
        if (t0 == e) k = 0; else if (t1 == e) k = 1;
        unsigned b = __ballot_sync(0xffffffffu, k >= 0);
        int pw = __popc(b & ((1u << lane) - 1u));
        if (lane == 0) wsum[wid] = __popc(b);
        __syncthreads();
        if (wid == 0) {
            int v = wsum[lane];
            int s = v;
#pragma unroll
            for (int o = 1; o < 32; o <<= 1) {
                int u = __shfl_up_sync(0xffffffffu, s, o);
                if (lane >= o) s += u;
            }
            wsum[lane] = s - v;
            if (lane == 31) total_s = s;
        }
        __syncthreads();
        if (k >= 0) {
            int pos = running + wsum[wid] + pw;
            if (pos < CAP) {
                g_row_token[e * CAP + pos] = n;
                g_slot[2 * n + k] = pos;
            } else {
                g_slot[2 * n + k] = -1;
            }
        }
        running += total_s;
        __syncthreads();
    }
    if (threadIdx.x == 0) g_load[e] = running < CAP ? running : CAP;
}

// ---------------- combine: out[t] = sum_k gate * O[e_k, slot_k] ------------
__global__ void combine_kernel(float* __restrict__ out) {
    int t = blockIdx.x * 8 + (threadIdx.x >> 5);
    int lane = threadIdx.x & 31;
    float4 acc[8];
#pragma unroll
    for (int i = 0; i < 8; i++) acc[i] = make_float4(0.f, 0.f, 0.f, 0.f);
#pragma unroll
    for (int k = 0; k < 2; k++) {
        int s = g_slot[2 * t + k];
        if (s >= 0) {
            int e = g_top[2 * t + k];
            float g = g_gate[2 * t + k];
            const float4* p = (const float4*)(g_O + ((size_t)e * CAP + s) * DIM);
#pragma unroll
            for (int i = 0; i < 8; i++) {
                float4 v = __ldg(p + lane + i * 32);
                acc[i].x += g * v.x; acc[i].y += g * v.y;
                acc[i].z += g * v.z; acc[i].w += g * v.w;
            }
        }
    }
    float4* o = (float4*)(out + (size_t)t * DIM);
#pragma unroll
    for (int i = 0; i < 8; i++) o[lane + i * 32] = acc[i];
}

// ---------------- stats -----------------------------------------------------
__global__ void stats_kernel(float* __restrict__ out) {
    if (threadIdx.x == 0) {
        float l[NE], s = 0.f;
#pragma unroll
        for (int e = 0; e < NE; e++) { l[e] = (float)g_load[e]; s += l[e]; }
        float inv = 1.f / (s + 1e-8f);
        float loss = 0.f;
#pragma unroll
        for (int e = 0; e < NE; e++) {
            float d = l[e] * inv;
            out[(size_t)NTOK * DIM + 1 + e] = d;
            loss -= d * logf(d + 1e-8f);
        }
        out[(size_t)NTOK * DIM] = loss;
    }
}

// ---------------- launch ----------------------------------------------------
extern "C" void kernel_launch(void* const* d_in, const int* in_sizes, int n_in,
                              void* d_out, int out_size) {
    const float* x  = (const float*)d_in[0];
    const float* Wr = (const float*)d_in[1];
    const float* br = (const float*)d_in[2];
    const float* W1 = (const float*)d_in[3];
    const float* b1 = (const float*)d_in[4];
    const float* W2 = (const float*)d_in[5];
    const float* b2 = (const float*)d_in[6];
    float* out = (float*)d_out;

    cudaFuncSetAttribute(moe_gemm<false>,
                         cudaFuncAttributeMaxDynamicSharedMemorySize, SMEM_DYN);
    cudaFuncSetAttribute(moe_gemm<true>,
                         cudaFuncAttributeMaxDynamicSharedMemorySize, SMEM_DYN);

    uint16_t *w1h, *w1l, *w2h, *w2l;
    cudaGetSymbolAddress((void**)&w1h, g_w1h);
    cudaGetSymbolAddress((void**)&w1l, g_w1l);
    cudaGetSymbolAddress((void**)&w2h, g_w2h);
    cudaGetSymbolAddress((void**)&w2l, g_w2l);

    const int wn4 = NE * DIM * DIM / 4;
    splitw_kernel<<<wn4 / 256, 256>>>((const float4*)W1, (uint2*)w1h, (uint2*)w1l, wn4);
    splitw_kernel<<<wn4 / 256, 256>>>((const float4*)W2, (uint2*)w2h, (uint2*)w2l, wn4);

    router_kernel<<<NTOK / 8, 256>>>(x, Wr, br);
    scan_kernel<<<NE, 1024>>>();
    dim3 grid(DIM / 128, CAP / 256, NE);
    moe_gemm<false><<<grid, 256, SMEM_DYN>>>(b1);
    moe_gemm<true><<<grid, 256, SMEM_DYN>>>(b2);
    combine_kernel<<<NTOK / 8, 256>>>(out);
    stats_kernel<<<1, 32>>>(out);
}

// round 8
// speedup vs baseline: 1.6946x; 1.1091x over previous
#include <cuda_runtime.h>
#include <cuda_fp16.h>
#include <cstdint>
#include <math.h>

#define NTOK 16384
#define DIM  1024
#define NE   8
#define CAP  2560          // int(1.25 * 16384 / 8)
#define BK   64
#define NCH  (DIM / BK)    // 16
#define PITCH 144          // 64 fp16 = 128B + 16B pad (conflict-free phases)
#define BH_OFF  36864      // 256*144
#define BL_OFF  55296      // BH_OFF + 128*144
#define STAGE_B 73728      // 256*144 + 256*144
#define SMEM_DYN (1024 + 3 * STAGE_B)   // 222208

// ---------------- device scratch (no allocation allowed) -------------------
__device__ int      g_top[NTOK * 2];
__device__ float    g_gate[NTOK * 2];
__device__ int      g_slot[NTOK * 2];
__device__ int      g_row_token[NE * CAP];
__device__ int      g_load[NE];
__device__ uint16_t g_xh[(size_t)NTOK * DIM];          // x as fp16
__device__ uint16_t g_w1h[(size_t)NE * DIM * DIM];     // W fp16 hi/lo
__device__ uint16_t g_w1l[(size_t)NE * DIM * DIM];
__device__ uint16_t g_w2h[(size_t)NE * DIM * DIM];
__device__ uint16_t g_w2l[(size_t)NE * DIM * DIM];
__device__ uint16_t g_Hh[(size_t)NE * CAP * DIM];      // hidden as fp16
__device__ float    g_O[(size_t)NE * CAP * DIM];       // expert out + b2

// ---------------- helpers ---------------------------------------------------
__device__ __forceinline__ uint32_t smem_u32(const void* p) {
    uint32_t a;
    asm("{ .reg .u64 t; cvta.to.shared.u64 t, %1; cvt.u32.u64 %0, t; }"
        : "=r"(a) : "l"(p));
    return a;
}
__device__ __forceinline__ void cpa16(uint32_t dst, const void* src) {
    asm volatile("cp.async.cg.shared.global [%0], [%1], 16;"
                 :: "r"(dst), "l"(src));
}
#define CP_COMMIT() asm volatile("cp.async.commit_group;" ::: "memory")
#define CP_WAIT1()  asm volatile("cp.async.wait_group 1;" ::: "memory")

__device__ __forceinline__ void ldsm4(uint32_t* r, uint32_t addr) {
    asm volatile("ldmatrix.sync.aligned.m8n8.x4.shared.b16 {%0,%1,%2,%3}, [%4];"
                 : "=r"(r[0]), "=r"(r[1]), "=r"(r[2]), "=r"(r[3]) : "r"(addr));
}
__device__ __forceinline__ void mma_f16(float* d, const uint32_t* a,
                                        const uint32_t* b) {
    asm volatile(
        "mma.sync.aligned.m16n8k16.row.col.f32.f16.f16.f32 "
        "{%0,%1,%2,%3}, {%4,%5,%6,%7}, {%8,%9}, {%0,%1,%2,%3};"
        : "+f"(d[0]), "+f"(d[1]), "+f"(d[2]), "+f"(d[3])
        : "r"(a[0]), "r"(a[1]), "r"(a[2]), "r"(a[3]), "r"(b[0]), "r"(b[1]));
}
__device__ __forceinline__ uint32_t cvt2h(float a, float b) {
    __half2 h = __floats2half2_rn(a, b);
    return *(uint32_t*)&h;
}
__device__ __forceinline__ void split2h(float a, float b,
                                        uint32_t& h, uint32_t& l) {
    __half2 hh = __floats2half2_rn(a, b);
    float2 bk = __half22float2(hh);
    __half2 ll = __floats2half2_rn(a - bk.x, b - bk.y);
    h = *(uint32_t*)&hh;
    l = *(uint32_t*)&ll;
}

// ---------------- W split: fp32 -> fp16 hi/lo ------------------------------
__global__ void splitw_kernel(const float4* __restrict__ src,
                              uint2* __restrict__ hi, uint2* __restrict__ lo,
                              int n4) {
    int i = blockIdx.x * blockDim.x + threadIdx.x;
    if (i >= n4) return;
    float4 v = src[i];
    uint32_t h0, l0, h1, l1;
    split2h(v.x, v.y, h0, l0);
    split2h(v.z, v.w, h1, l1);
    hi[i] = make_uint2(h0, h1);
    lo[i] = make_uint2(l0, l1);
}

// ---------------- router + x->fp16 conversion (fused) ----------------------
__global__ void router_kernel(const float* __restrict__ x,
                              const float* __restrict__ Wr,
                              const float* __restrict__ br) {
    int token = (blockIdx.x * blockDim.x + threadIdx.x) >> 5;
    int lane  = threadIdx.x & 31;
    if (token >= NTOK) return;
    const float4* xr = (const float4*)(x + (size_t)token * DIM);
    uint2* xo = (uint2*)(g_xh + (size_t)token * DIM);
    float acc[NE];
#pragma unroll
    for (int e = 0; e < NE; e++) acc[e] = 0.f;
#pragma unroll
    for (int i = 0; i < 8; i++) {
        const int d4 = lane + i * 32;
        float4 v = __ldg(xr + d4);
        xo[d4] = make_uint2(cvt2h(v.x, v.y), cvt2h(v.z, v.w));
#pragma unroll
        for (int e = 0; e < NE; e++) {
            const float4 w = __ldg((const float4*)(Wr + e * DIM) + d4);
            acc[e] += v.x * w.x + v.y * w.y + v.z * w.z + v.w * w.w;
        }
    }
#pragma unroll
    for (int e = 0; e < NE; e++)
#pragma unroll
        for (int o = 16; o; o >>= 1)
            acc[e] += __shfl_xor_sync(0xffffffffu, acc[e], o);
    if (lane == 0) {
        float l[NE];
#pragma unroll
        for (int e = 0; e < NE; e++) l[e] = acc[e] + br[e];
        float v1 = -3.4e38f; int i1 = 0;
#pragma unroll
        for (int e = 0; e < NE; e++) if (l[e] > v1) { v1 = l[e]; i1 = e; }
        float v2 = -3.4e38f; int i2 = 0;
#pragma unroll
        for (int e = 0; e < NE; e++) if (e != i1 && l[e] > v2) { v2 = l[e]; i2 = e; }
        float ex = expf(v2 - v1);
        float inv = 1.f / (1.f + ex);
        g_top[2 * token]      = i1;
        g_top[2 * token + 1]  = i2;
        g_gate[2 * token]     = inv;
        g_gate[2 * token + 1] = ex * inv;
    }
}

// ---------------- tensor-core (HMMA fp16) GEMM, both layers ----------------
// C[256x128] = A[256x1024] @ W[e][128x1024]^T  (+bias; relu+cvt for G1)
// 2-term fp16 split: A*Wh + A*Wl, fp32 accumulate.
// BK=64, 3-stage cp.async ring, ONE __syncthreads per chunk.
template <bool G2>
__global__ void __launch_bounds__(256)
moe_gemm(const float* __restrict__ bias) {
    extern __shared__ __align__(16) char dsm[];
    int* rows = (int*)dsm;

    const int e = blockIdx.z;
    const int loadE = g_load[e];
    const int m0 = blockIdx.y * 256;
    if (m0 >= loadE) return;
    const int n0 = blockIdx.x * 128;
    const int tid = threadIdx.x;
    const int lane = tid & 31, wid = tid >> 5;
    const int wm = wid >> 1, wn = wid & 1;     // warp tile 64x64
    const uint32_t sb = smem_u32(dsm);

    if (!G2) {
        int m = m0 + tid;
        rows[tid] = g_row_token[e * CAP + (m < loadE ? m : loadE - 1)];
    }
    __syncthreads();

    // cp.async: thread tid -> A row tid (8x16B); B row tid&127 of hi
    // (tid<128) or lo (tid>=128) (8x16B)
    size_t abase = G2 ? ((size_t)e * CAP + m0 + tid) * DIM
                      : (size_t)rows[tid] * DIM;
    const uint16_t* pA = (G2 ? g_Hh : g_xh) + abase;
    const uint32_t dA = (uint32_t)tid * PITCH;
    const uint16_t* wsrc = G2 ? (tid < 128 ? g_w2h : g_w2l)
                              : (tid < 128 ? g_w1h : g_w1l);
    const uint16_t* pB = wsrc + ((size_t)e * DIM + n0 + (tid & 127)) * DIM;
    const uint32_t dB = BH_OFF + (uint32_t)(tid >> 7) * (BL_OFF - BH_OFF)
                      + (uint32_t)(tid & 127) * PITCH;

    auto issue = [&](int c, uint32_t st) {
        const int k0 = c * BK;
        const uint16_t* sa = pA + k0;
        const uint16_t* sbp = pB + k0;
#pragma unroll
        for (int q = 0; q < 8; q++) {
            cpa16(st + dA + q * 16, sa + q * 8);
            cpa16(st + dB + q * 16, sbp + q * 8);
        }
    };

    // ldmatrix fragment offsets (stage-relative)
    uint32_t aoff[4], boff[4];
#pragma unroll
    for (int ms = 0; ms < 4; ms++)
        aoff[ms] = (uint32_t)(wm * 64 + ms * 16 + (lane & 15)) * PITCH
                 + (uint32_t)(lane >> 4) * 16;
#pragma unroll
    for (int np = 0; np < 4; np++)
        boff[np] = BH_OFF
                 + (uint32_t)(wn * 64 + np * 16 + (lane & 7) + ((lane >> 4) & 1) * 8)
                 * PITCH + (uint32_t)((lane >> 3) & 1) * 16;

    float acc[4][8][4];
#pragma unroll
    for (int i = 0; i < 4; i++)
#pragma unroll
        for (int j = 0; j < 8; j++)
#pragma unroll
            for (int k = 0; k < 4; k++) acc[i][j][k] = 0.f;

    auto compute = [&](uint32_t st) {
#pragma unroll
        for (int s = 0; s < 4; s++) {              // 4 k16-steps per BK=64
            uint32_t ah[4][4], bh[8][2], bl[8][2];
#pragma unroll
            for (int ms = 0; ms < 4; ms++)
                ldsm4(ah[ms], st + aoff[ms] + s * 32);
#pragma unroll
            for (int np = 0; np < 4; np++) {
                uint32_t t[4];
                ldsm4(t, st + boff[np] + s * 32);
                bh[2 * np][0] = t[0]; bh[2 * np][1] = t[1];
                bh[2 * np + 1][0] = t[2]; bh[2 * np + 1][1] = t[3];
                ldsm4(t, st + boff[np] + (BL_OFF - BH_OFF) + s * 32);
                bl[2 * np][0] = t[0]; bl[2 * np][1] = t[1];
                bl[2 * np + 1][0] = t[2]; bl[2 * np + 1][1] = t[3];
            }
#pragma unroll
            for (int ms = 0; ms < 4; ms++)
#pragma unroll
                for (int ns = 0; ns < 8; ns++) {
                    mma_f16(acc[ms][ns], ah[ms], bh[ns]);
                    mma_f16(acc[ms][ns], ah[ms], bl[ns]);
                }
        }
    };

    const uint32_t st0 = sb + 1024;
    issue(0, st0);           CP_COMMIT();
    issue(1, st0 + STAGE_B); CP_COMMIT();

    int stg = 0;
#pragma unroll 1
    for (int c = 0; c < NCH; c++) {
        CP_WAIT1();
        __syncthreads();
        compute(st0 + (uint32_t)stg * STAGE_B);
        // write stage (c+2)%3 == (c-1)%3: finished by all warps (post-sync)
        if (c + 2 < NCH) {
            int ns = stg + 2; if (ns >= 3) ns -= 3;
            issue(c + 2, st0 + (uint32_t)ns * STAGE_B);
        }
        CP_COMMIT();                       // always commit (empty group ok)
        stg = (stg == 2) ? 0 : stg + 1;
    }

    // ---- epilogue ----
    const float* bE = bias + e * DIM;
#pragma unroll
    for (int ms = 0; ms < 4; ms++) {
        const int row = m0 + wm * 64 + ms * 16 + (lane >> 2);
#pragma unroll
        for (int ns = 0; ns < 8; ns++) {
            const int col = n0 + wn * 64 + ns * 8 + 2 * (lane & 3);
            const float2 bv = *(const float2*)(bE + col);
            float2 v0, v1;
            v0.x = acc[ms][ns][0] + bv.x; v0.y = acc[ms][ns][1] + bv.y;
            v1.x = acc[ms][ns][2] + bv.x; v1.y = acc[ms][ns][3] + bv.y;
            const size_t idx0 = ((size_t)e * CAP + row) * DIM + col;
            if (G2) {
                *(float2*)(g_O + idx0) = v0;
                *(float2*)(g_O + idx0 + 8 * DIM) = v1;
            } else {
                v0.x = v0.x > 0.f ? v0.x : 0.f; v0.y = v0.y > 0.f ? v0.y : 0.f;
                v1.x = v1.x > 0.f ? v1.x : 0.f; v1.y = v1.y > 0.f ? v1.y : 0.f;
                *(uint32_t*)(g_Hh + idx0) = cvt2h(v0.x, v0.y);
                *(uint32_t*)(g_Hh + idx0 + 8 * DIM) = cvt2h(v1.x, v1.y);
            }
        }
    }
}

// ---------------- dispatch scan --------------------------------------------
__global__ void scan_kernel() {
    int e = blockIdx.x;
    __shared__ int wsum[32];
    __shared__ int total_s;
    int lane = threadIdx.x & 31;
    int wid  = threadIdx.x >> 5;
    int running = 0;
    for (int base = 0; base < NTOK; base += 1024) {
        int n = base + threadIdx.x;
        int k = -1;
        int t0 = g_top[2 * n], t1 = g_top[2 * n + 1];
        if (t0 == e) k = 0; else if (t1 == e) k = 1;
        unsigned b = __ballot_sync(0xffffffffu, k >= 0);
        int pw = __popc(b & ((1u << lane) - 1u));
        if (lane == 0) wsum[wid] = __popc(b);
        __syncthreads();
        if (wid == 0) {
            int v = wsum[lane];
            int s = v;
#pragma unroll
            for (int o = 1; o < 32; o <<= 1) {
                int u = __shfl_up_sync(0xffffffffu, s, o);
                if (lane >= o) s += u;
            }
            wsum[lane] = s - v;
            if (lane == 31) total_s = s;
        }
        __syncthreads();
        if (k >= 0) {
            int pos = running + wsum[wid] + pw;
            if (pos < CAP) {
                g_row_token[e * CAP + pos] = n;
                g_slot[2 * n + k] = pos;
            } else {
                g_slot[2 * n + k] = -1;
            }
        }
        running += total_s;
        __syncthreads();
    }
    if (threadIdx.x == 0) g_load[e] = running < CAP ? running : CAP;
}

// ---------------- combine: out[t] = sum_k gate * O[e_k, slot_k] ------------
__global__ void combine_kernel(float* __restrict__ out) {
    int t = blockIdx.x * 8 + (threadIdx.x >> 5);
    int lane = threadIdx.x & 31;
    float4 acc[8];
#pragma unroll
    for (int i = 0; i < 8; i++) acc[i] = make_float4(0.f, 0.f, 0.f, 0.f);
#pragma unroll
    for (int k = 0; k < 2; k++) {
        int s = g_slot[2 * t + k];
        if (s >= 0) {
            int e = g_top[2 * t + k];
            float g = g_gate[2 * t + k];
            const float4* p = (const float4*)(g_O + ((size_t)e * CAP + s) * DIM);
#pragma unroll
            for (int i = 0; i < 8; i++) {
                float4 v = __ldg(p + lane + i * 32);
                acc[i].x += g * v.x; acc[i].y += g * v.y;
                acc[i].z += g * v.z; acc[i].w += g * v.w;
            }
        }
    }
    float4* o = (float4*)(out + (size_t)t * DIM);
#pragma unroll
    for (int i = 0; i < 8; i++) o[lane + i * 32] = acc[i];
}

// ---------------- stats -----------------------------------------------------
__global__ void stats_kernel(float* __restrict__ out) {
    if (threadIdx.x == 0) {
        float l[NE], s = 0.f;
#pragma unroll
        for (int e = 0; e < NE; e++) { l[e] = (float)g_load[e]; s += l[e]; }
        float inv = 1.f / (s + 1e-8f);
        float loss = 0.f;
#pragma unroll
        for (int e = 0; e < NE; e++) {
            float d = l[e] * inv;
            out[(size_t)NTOK * DIM + 1 + e] = d;
            loss -= d * logf(d + 1e-8f);
        }
        out[(size_t)NTOK * DIM] = loss;
    }
}

// ---------------- launch ----------------------------------------------------
extern "C" void kernel_launch(void* const* d_in, const int* in_sizes, int n_in,
                              void* d_out, int out_size) {
    const float* x  = (const float*)d_in[0];
    const float* Wr = (const float*)d_in[1];
    const float* br = (const float*)d_in[2];
    const float* W1 = (const float*)d_in[3];
    const float* b1 = (const float*)d_in[4];
    const float* W2 = (const float*)d_in[5];
    const float* b2 = (const float*)d_in[6];
    float* out = (float*)d_out;

    cudaFuncSetAttribute(moe_gemm<false>,
                         cudaFuncAttributeMaxDynamicSharedMemorySize, SMEM_DYN);
    cudaFuncSetAttribute(moe_gemm<true>,
                         cudaFuncAttributeMaxDynamicSharedMemorySize, SMEM_DYN);

    uint16_t *w1h, *w1l, *w2h, *w2l;
    cudaGetSymbolAddress((void**)&w1h, g_w1h);
    cudaGetSymbolAddress((void**)&w1l, g_w1l);
    cudaGetSymbolAddress((void**)&w2h, g_w2h);
    cudaGetSymbolAddress((void**)&w2l, g_w2l);

    const int wn4 = NE * DIM * DIM / 4;
    splitw_kernel<<<wn4 / 256, 256>>>((const float4*)W1, (uint2*)w1h, (uint2*)w1l, wn4);
    splitw_kernel<<<wn4 / 256, 256>>>((const float4*)W2, (uint2*)w2h, (uint2*)w2l, wn4);

    router_kernel<<<NTOK / 8, 256>>>(x, Wr, br);
    scan_kernel<<<NE, 1024>>>();
    dim3 grid(DIM / 128, CAP / 256, NE);
    moe_gemm<false><<<grid, 256, SMEM_DYN>>>(b1);
    moe_gemm<true><<<grid, 256, SMEM_DYN>>>(b2);
    combine_kernel<<<NTOK / 8, 256>>>(out);
    stats_kernel<<<1, 32>>>(out);
}

// round 9
// speedup vs baseline: 2.3758x; 1.4020x over previous
#include <cuda_runtime.h>
#include <cuda_fp16.h>
#include <cstdint>
#include <math.h>

#define NTOK 16384
#define DIM  1024
#define NE   8
#define CAP  2560          // int(1.25 * 16384 / 8)
#define BK   64
#define NCH  (DIM / BK)    // 16
#define PITCH 144          // 64 fp16 = 128B + 16B pad (conflict-free phases)
#define BH_OFF  36864      // 256*144 (A tile)
#define STAGE_B 55296      // A 36864 + B 18432
#define SMEM_DYN (1024 + 3 * STAGE_B)   // 166912

// ---------------- device scratch (no allocation allowed) -------------------
__device__ int      g_top[NTOK * 2];
__device__ float    g_gate[NTOK * 2];
__device__ int      g_slot[NTOK * 2];
__device__ int      g_row_token[NE * CAP];
__device__ int      g_load[NE];
__device__ uint16_t g_xh[(size_t)NTOK * DIM];          // x as fp16
__device__ uint16_t g_w1h[(size_t)NE * DIM * DIM];     // W1 as fp16
__device__ uint16_t g_w2h[(size_t)NE * DIM * DIM];     // W2 as fp16
__device__ uint16_t g_Hh[(size_t)NE * CAP * DIM];      // hidden as fp16
__device__ float    g_O[(size_t)NE * CAP * DIM];       // expert out + b2

// ---------------- helpers ---------------------------------------------------
__device__ __forceinline__ uint32_t smem_u32(const void* p) {
    uint32_t a;
    asm("{ .reg .u64 t; cvta.to.shared.u64 t, %1; cvt.u32.u64 %0, t; }"
        : "=r"(a) : "l"(p));
    return a;
}
__device__ __forceinline__ void cpa16(uint32_t dst, const void* src) {
    asm volatile("cp.async.cg.shared.global [%0], [%1], 16;"
                 :: "r"(dst), "l"(src));
}
#define CP_COMMIT() asm volatile("cp.async.commit_group;" ::: "memory")
#define CP_WAIT1()  asm volatile("cp.async.wait_group 1;" ::: "memory")

__device__ __forceinline__ void ldsm4(uint32_t* r, uint32_t addr) {
    asm volatile("ldmatrix.sync.aligned.m8n8.x4.shared.b16 {%0,%1,%2,%3}, [%4];"
                 : "=r"(r[0]), "=r"(r[1]), "=r"(r[2]), "=r"(r[3]) : "r"(addr));
}
__device__ __forceinline__ void mma_f16(float* d, const uint32_t* a,
                                        const uint32_t* b) {
    asm volatile(
        "mma.sync.aligned.m16n8k16.row.col.f32.f16.f16.f32 "
        "{%0,%1,%2,%3}, {%4,%5,%6,%7}, {%8,%9}, {%0,%1,%2,%3};"
        : "+f"(d[0]), "+f"(d[1]), "+f"(d[2]), "+f"(d[3])
        : "r"(a[0]), "r"(a[1]), "r"(a[2]), "r"(a[3]), "r"(b[0]), "r"(b[1]));
}
__device__ __forceinline__ uint32_t cvt2h(float a, float b) {
    __half2 h = __floats2half2_rn(a, b);
    return *(uint32_t*)&h;
}

// ---------------- W convert: fp32 -> fp16 ----------------------------------
__global__ void cvtw_kernel(const float4* __restrict__ src,
                            uint2* __restrict__ dst, int n4) {
    int i = blockIdx.x * blockDim.x + threadIdx.x;
    if (i >= n4) return;
    float4 v = src[i];
    dst[i] = make_uint2(cvt2h(v.x, v.y), cvt2h(v.z, v.w));
}

// ---------------- router + x->fp16 conversion (fused) ----------------------
__global__ void router_kernel(const float* __restrict__ x,
                              const float* __restrict__ Wr,
                              const float* __restrict__ br) {
    int token = (blockIdx.x * blockDim.x + threadIdx.x) >> 5;
    int lane  = threadIdx.x & 31;
    if (token >= NTOK) return;
    const float4* xr = (const float4*)(x + (size_t)token * DIM);
    uint2* xo = (uint2*)(g_xh + (size_t)token * DIM);
    float acc[NE];
#pragma unroll
    for (int e = 0; e < NE; e++) acc[e] = 0.f;
#pragma unroll
    for (int i = 0; i < 8; i++) {
        const int d4 = lane + i * 32;
        float4 v = __ldg(xr + d4);
        xo[d4] = make_uint2(cvt2h(v.x, v.y), cvt2h(v.z, v.w));
#pragma unroll
        for (int e = 0; e < NE; e++) {
            const float4 w = __ldg((const float4*)(Wr + e * DIM) + d4);
            acc[e] += v.x * w.x + v.y * w.y + v.z * w.z + v.w * w.w;
        }
    }
#pragma unroll
    for (int e = 0; e < NE; e++)
#pragma unroll
        for (int o = 16; o; o >>= 1)
            acc[e] += __shfl_xor_sync(0xffffffffu, acc[e], o);
    if (lane == 0) {
        float l[NE];
#pragma unroll
        for (int e = 0; e < NE; e++) l[e] = acc[e] + br[e];
        float v1 = -3.4e38f; int i1 = 0;
#pragma unroll
        for (int e = 0; e < NE; e++) if (l[e] > v1) { v1 = l[e]; i1 = e; }
        float v2 = -3.4e38f; int i2 = 0;
#pragma unroll
        for (int e = 0; e < NE; e++) if (e != i1 && l[e] > v2) { v2 = l[e]; i2 = e; }
        float ex = expf(v2 - v1);
        float inv = 1.f / (1.f + ex);
        g_top[2 * token]      = i1;
        g_top[2 * token + 1]  = i2;
        g_gate[2 * token]     = inv;
        g_gate[2 * token + 1] = ex * inv;
    }
}

// ---------------- tensor-core (HMMA fp16) GEMM, both layers ----------------
// C[256x128] = A[256x1024] @ W[e][128x1024]^T  (+bias; relu+cvt for G1)
// Plain fp16 operands, fp32 accumulate. BK=64, 3-stage ring, 1 sync/chunk.
template <bool G2>
__global__ void __launch_bounds__(256)
moe_gemm(const float* __restrict__ bias) {
    extern __shared__ __align__(16) char dsm[];
    int* rows = (int*)dsm;

    const int e = blockIdx.z;
    const int loadE = g_load[e];
    const int m0 = blockIdx.y * 256;
    if (m0 >= loadE) return;
    const int n0 = blockIdx.x * 128;
    const int tid = threadIdx.x;
    const int lane = tid & 31, wid = tid >> 5;
    const int wm = wid >> 1, wn = wid & 1;     // warp tile 64x64
    const uint32_t sb = smem_u32(dsm);

    if (!G2) {
        int m = m0 + tid;
        rows[tid] = g_row_token[e * CAP + (m < loadE ? m : loadE - 1)];
    }
    __syncthreads();

    // cp.async: every thread loads A row tid (8x16B);
    // threads 0..127 additionally load B row tid (8x16B)
    size_t abase = G2 ? ((size_t)e * CAP + m0 + tid) * DIM
                      : (size_t)rows[tid] * DIM;
    const uint16_t* pA = (G2 ? g_Hh : g_xh) + abase;
    const uint32_t dA = (uint32_t)tid * PITCH;
    const uint16_t* wsrc = G2 ? g_w2h : g_w1h;
    const uint16_t* pB = wsrc + ((size_t)e * DIM + n0 + (tid & 127)) * DIM;
    const uint32_t dB = BH_OFF + (uint32_t)(tid & 127) * PITCH;

    auto issue = [&](int c, uint32_t st) {
        const int k0 = c * BK;
        const uint16_t* sa = pA + k0;
#pragma unroll
        for (int q = 0; q < 8; q++) cpa16(st + dA + q * 16, sa + q * 8);
        if (tid < 128) {
            const uint16_t* sbp = pB + k0;
#pragma unroll
            for (int q = 0; q < 8; q++) cpa16(st + dB + q * 16, sbp + q * 8);
        }
    };

    // ldmatrix fragment offsets (stage-relative)
    uint32_t aoff[4], boff[4];
#pragma unroll
    for (int ms = 0; ms < 4; ms++)
        aoff[ms] = (uint32_t)(wm * 64 + ms * 16 + (lane & 15)) * PITCH
                 + (uint32_t)(lane >> 4) * 16;
#pragma unroll
    for (int np = 0; np < 4; np++)
        boff[np] = BH_OFF
                 + (uint32_t)(wn * 64 + np * 16 + (lane & 7) + ((lane >> 4) & 1) * 8)
                 * PITCH + (uint32_t)((lane >> 3) & 1) * 16;

    float acc[4][8][4];
#pragma unroll
    for (int i = 0; i < 4; i++)
#pragma unroll
        for (int j = 0; j < 8; j++)
#pragma unroll
            for (int k = 0; k < 4; k++) acc[i][j][k] = 0.f;

    auto compute = [&](uint32_t st) {
#pragma unroll
        for (int s = 0; s < 4; s++) {              // 4 k16-steps per BK=64
            uint32_t ah[4][4], bh[8][2];
#pragma unroll
            for (int ms = 0; ms < 4; ms++)
                ldsm4(ah[ms], st + aoff[ms] + s * 32);
#pragma unroll
            for (int np = 0; np < 4; np++) {
                uint32_t t[4];
                ldsm4(t, st + boff[np] + s * 32);
                bh[2 * np][0] = t[0]; bh[2 * np][1] = t[1];
                bh[2 * np + 1][0] = t[2]; bh[2 * np + 1][1] = t[3];
            }
#pragma unroll
            for (int ms = 0; ms < 4; ms++)
#pragma unroll
                for (int ns = 0; ns < 8; ns++)
                    mma_f16(acc[ms][ns], ah[ms], bh[ns]);
        }
    };

    const uint32_t st0 = sb + 1024;
    issue(0, st0);           CP_COMMIT();
    issue(1, st0 + STAGE_B); CP_COMMIT();

    int stg = 0;
#pragma unroll 1
    for (int c = 0; c < NCH; c++) {
        CP_WAIT1();
        __syncthreads();
        compute(st0 + (uint32_t)stg * STAGE_B);
        // write stage (c+2)%3 == (c-1)%3: finished by all warps (post-sync)
        if (c + 2 < NCH) {
            int ns = stg + 2; if (ns >= 3) ns -= 3;
            issue(c + 2, st0 + (uint32_t)ns * STAGE_B);
        }
        CP_COMMIT();                       // always commit (empty group ok)
        stg = (stg == 2) ? 0 : stg + 1;
    }

    // ---- epilogue ----
    const float* bE = bias + e * DIM;
#pragma unroll
    for (int ms = 0; ms < 4; ms++) {
        const int row = m0 + wm * 64 + ms * 16 + (lane >> 2);
#pragma unroll
        for (int ns = 0; ns < 8; ns++) {
            const int col = n0 + wn * 64 + ns * 8 + 2 * (lane & 3);
            const float2 bv = *(const float2*)(bE + col);
            float2 v0, v1;
            v0.x = acc[ms][ns][0] + bv.x; v0.y = acc[ms][ns][1] + bv.y;
            v1.x = acc[ms][ns][2] + bv.x; v1.y = acc[ms][ns][3] + bv.y;
            const size_t idx0 = ((size_t)e * CAP + row) * DIM + col;
            if (G2) {
                *(float2*)(g_O + idx0) = v0;
                *(float2*)(g_O + idx0 + 8 * DIM) = v1;
            } else {
                v0.x = v0.x > 0.f ? v0.x : 0.f; v0.y = v0.y > 0.f ? v0.y : 0.f;
                v1.x = v1.x > 0.f ? v1.x : 0.f; v1.y = v1.y > 0.f ? v1.y : 0.f;
                *(uint32_t*)(g_Hh + idx0) = cvt2h(v0.x, v0.y);
                *(uint32_t*)(g_Hh + idx0 + 8 * DIM) = cvt2h(v1.x, v1.y);
            }
        }
    }
}

// ---------------- dispatch scan --------------------------------------------
__global__ void scan_kernel() {
    int e = blockIdx.x;
    __shared__ int wsum[32];
    __shared__ int total_s;
    int lane = threadIdx.x & 31;
    int wid  = threadIdx.x >> 5;
    int running = 0;
    for (int base = 0; base < NTOK; base += 1024) {
        int n = base + threadIdx.x;
        int k = -1;
        int t0 = g_top[2 * n], t1 = g_top[2 * n + 1];
        if (t0 == e) k = 0; else if (t1 == e) k = 1;
        unsigned b = __ballot_sync(0xffffffffu, k >= 0);
        int pw = __popc(b & ((1u << lane) - 1u));
        if (lane == 0) wsum[wid] = __popc(b);
        __syncthreads();
        if (wid == 0) {
            int v = wsum[lane];
            int s = v;
#pragma unroll
            for (int o = 1; o < 32; o <<= 1) {
                int u = __shfl_up_sync(0xffffffffu, s, o);
                if (lane >= o) s += u;
            }
            wsum[lane] = s - v;
            if (lane == 31) total_s = s;
        }
        __syncthreads();
        if (k >= 0) {
            int pos = running + wsum[wid] + pw;
            if (pos < CAP) {
                g_row_token[e * CAP + pos] = n;
                g_slot[2 * n + k] = pos;
            } else {
                g_slot[2 * n + k] = -1;
            }
        }
        running += total_s;
        __syncthreads();
    }
    if (threadIdx.x == 0) g_load[e] = running < CAP ? running : CAP;
}

// ---------------- combine: out[t] = sum_k gate * O[e_k, slot_k] ------------
__global__ void combine_kernel(float* __restrict__ out) {
    int t = blockIdx.x * 8 + (threadIdx.x >> 5);
    int lane = threadIdx.x & 31;
    float4 acc[8];
#pragma unroll
    for (int i = 0; i < 8; i++) acc[i] = make_float4(0.f, 0.f, 0.f, 0.f);
#pragma unroll
    for (int k = 0; k < 2; k++) {
        int s = g_slot[2 * t + k];
        if (s >= 0) {
            int e = g_top[2 * t + k];
            float g = g_gate[2 * t + k];
            const float4* p = (const float4*)(g_O + ((size_t)e * CAP + s) * DIM);
#pragma unroll
            for (int i = 0; i < 8; i++) {
                float4 v = __ldg(p + lane + i * 32);
                acc[i].x += g * v.x; acc[i].y += g * v.y;
                acc[i].z += g * v.z; acc[i].w += g * v.w;
            }
        }
    }
    float4* o = (float4*)(out + (size_t)t * DIM);
#pragma unroll
    for (int i = 0; i < 8; i++) o[lane + i * 32] = acc[i];
}

// ---------------- stats -----------------------------------------------------
__global__ void stats_kernel(float* __restrict__ out) {
    if (threadIdx.x == 0) {
        float l[NE], s = 0.f;
#pragma unroll
        for (int e = 0; e < NE; e++) { l[e] = (float)g_load[e]; s += l[e]; }
        float inv = 1.f / (s + 1e-8f);
        float loss = 0.f;
#pragma unroll
        for (int e = 0; e < NE; e++) {
            float d = l[e] * inv;
            out[(size_t)NTOK * DIM + 1 + e] = d;
            loss -= d * logf(d + 1e-8f);
        }
        out[(size_t)NTOK * DIM] = loss;
    }
}

// ---------------- launch ----------------------------------------------------
extern "C" void kernel_launch(void* const* d_in, const int* in_sizes, int n_in,
                              void* d_out, int out_size) {
    const float* x  = (const float*)d_in[0];
    const float* Wr = (const float*)d_in[1];
    const float* br = (const float*)d_in[2];
    const float* W1 = (const float*)d_in[3];
    const float* b1 = (const float*)d_in[4];
    const float* W2 = (const float*)d_in[5];
    const float* b2 = (const float*)d_in[6];
    float* out = (float*)d_out;

    cudaFuncSetAttribute(moe_gemm<false>,
                         cudaFuncAttributeMaxDynamicSharedMemorySize, SMEM_DYN);
    cudaFuncSetAttribute(moe_gemm<true>,
                         cudaFuncAttributeMaxDynamicSharedMemorySize, SMEM_DYN);

    uint16_t *w1h, *w2h;
    cudaGetSymbolAddress((void**)&w1h, g_w1h);
    cudaGetSymbolAddress((void**)&w2h, g_w2h);

    const int wn4 = NE * DIM * DIM / 4;
    cvtw_kernel<<<wn4 / 256, 256>>>((const float4*)W1, (uint2*)w1h, wn4);
    cvtw_kernel<<<wn4 / 256, 256>>>((const float4*)W2, (uint2*)w2h, wn4);

    router_kernel<<<NTOK / 8, 256>>>(x, Wr, br);
    scan_kernel<<<NE, 1024>>>();
    dim3 grid(DIM / 128, CAP / 256, NE);
    moe_gemm<false><<<grid, 256, SMEM_DYN>>>(b1);
    moe_gemm<true><<<grid, 256, SMEM_DYN>>>(b2);
    combine_kernel<<<NTOK / 8, 256>>>(out);
    stats_kernel<<<1, 32>>>(out);
}

// round 10
// speedup vs baseline: 2.3996x; 1.0100x over previous
#include <cuda_runtime.h>
#include <cuda_fp16.h>
#include <cstdint>
#include <math.h>

#define NTOK 16384
#define DIM  1024
#define NE   8
#define CAP  2560          // int(1.25 * 16384 / 8)
#define BK   64
#define NCH  (DIM / BK)    // 16
#define PITCH 144          // 64 fp16 = 128B + 16B pad (conflict-free phases)
#define BH_OFF  36864      // 256*144 (A tile)
#define STAGE_B 55296      // A 36864 + B 18432
#define SMEM_DYN (1024 + 3 * STAGE_B)   // 166912
#define TILES_PER_E 80     // 10 m-tiles x 8 n-tiles
#define G1_ITEMS (NE * TILES_PER_E)     // 640
#define TOTAL_ITEMS (2 * G1_ITEMS)      // 1280
#define GRID_PERSIST 152

// ---------------- device scratch (no allocation allowed) -------------------
__device__ int      g_top[NTOK * 2];
__device__ float    g_gate[NTOK * 2];
__device__ int      g_slot[NTOK * 2];
__device__ int      g_row_token[NE * CAP];
__device__ float    g_row_gate[NE * CAP];
__device__ int      g_load[NE];
__device__ int      g_next;                            // work-queue cursor
__device__ int      g_done[NE];                        // gemm1 tiles done / expert
__device__ uint16_t g_xh[(size_t)NTOK * DIM];          // x as fp16
__device__ uint16_t g_w1h[(size_t)NE * DIM * DIM];     // W1 as fp16
__device__ uint16_t g_w2h[(size_t)NE * DIM * DIM];     // W2 as fp16
__device__ uint16_t g_Hh[(size_t)NE * CAP * DIM];      // hidden as fp16
__device__ uint16_t g_Oh[(size_t)NE * CAP * DIM];      // gated expert out, fp16

// ---------------- helpers ---------------------------------------------------
__device__ __forceinline__ uint32_t smem_u32(const void* p) {
    uint32_t a;
    asm("{ .reg .u64 t; cvta.to.shared.u64 t, %1; cvt.u32.u64 %0, t; }"
        : "=r"(a) : "l"(p));
    return a;
}
__device__ __forceinline__ void cpa16(uint32_t dst, const void* src) {
    asm volatile("cp.async.cg.shared.global [%0], [%1], 16;"
                 :: "r"(dst), "l"(src));
}
#define CP_COMMIT() asm volatile("cp.async.commit_group;" ::: "memory")
#define CP_WAIT1()  asm volatile("cp.async.wait_group 1;" ::: "memory")

__device__ __forceinline__ void ldsm4(uint32_t* r, uint32_t addr) {
    asm volatile("ldmatrix.sync.aligned.m8n8.x4.shared.b16 {%0,%1,%2,%3}, [%4];"
                 : "=r"(r[0]), "=r"(r[1]), "=r"(r[2]), "=r"(r[3]) : "r"(addr));
}
__device__ __forceinline__ void mma_f16(float* d, const uint32_t* a,
                                        const uint32_t* b) {
    asm volatile(
        "mma.sync.aligned.m16n8k16.row.col.f32.f16.f16.f32 "
        "{%0,%1,%2,%3}, {%4,%5,%6,%7}, {%8,%9}, {%0,%1,%2,%3};"
        : "+f"(d[0]), "+f"(d[1]), "+f"(d[2]), "+f"(d[3])
        : "r"(a[0]), "r"(a[1]), "r"(a[2]), "r"(a[3]), "r"(b[0]), "r"(b[1]));
}
__device__ __forceinline__ uint32_t cvt2h(float a, float b) {
    __half2 h = __floats2half2_rn(a, b);
    return *(uint32_t*)&h;
}
__device__ __forceinline__ int ld_acq(const int* p) {
    int v;
    asm volatile("ld.acquire.gpu.global.b32 %0, [%1];" : "=r"(v) : "l"(p));
    return v;
}

// ---------------- W convert: fp32 -> fp16 ----------------------------------
__global__ void cvtw_kernel(const float4* __restrict__ src,
                            uint2* __restrict__ dst, int n4) {
    int i = blockIdx.x * blockDim.x + threadIdx.x;
    if (i >= n4) return;
    float4 v = src[i];
    dst[i] = make_uint2(cvt2h(v.x, v.y), cvt2h(v.z, v.w));
}

// ---------------- router + x->fp16 conversion (fused) ----------------------
__global__ void router_kernel(const float* __restrict__ x,
                              const float* __restrict__ Wr,
                              const float* __restrict__ br) {
    int token = (blockIdx.x * blockDim.x + threadIdx.x) >> 5;
    int lane  = threadIdx.x & 31;
    if (token >= NTOK) return;
    const float4* xr = (const float4*)(x + (size_t)token * DIM);
    uint2* xo = (uint2*)(g_xh + (size_t)token * DIM);
    float acc[NE];
#pragma unroll
    for (int e = 0; e < NE; e++) acc[e] = 0.f;
#pragma unroll
    for (int i = 0; i < 8; i++) {
        const int d4 = lane + i * 32;
        float4 v = __ldg(xr + d4);
        xo[d4] = make_uint2(cvt2h(v.x, v.y), cvt2h(v.z, v.w));
#pragma unroll
        for (int e = 0; e < NE; e++) {
            const float4 w = __ldg((const float4*)(Wr + e * DIM) + d4);
            acc[e] += v.x * w.x + v.y * w.y + v.z * w.z + v.w * w.w;
        }
    }
#pragma unroll
    for (int e = 0; e < NE; e++)
#pragma unroll
        for (int o = 16; o; o >>= 1)
            acc[e] += __shfl_xor_sync(0xffffffffu, acc[e], o);
    if (lane == 0) {
        float l[NE];
#pragma unroll
        for (int e = 0; e < NE; e++) l[e] = acc[e] + br[e];
        float v1 = -3.4e38f; int i1 = 0;
#pragma unroll
        for (int e = 0; e < NE; e++) if (l[e] > v1) { v1 = l[e]; i1 = e; }
        float v2 = -3.4e38f; int i2 = 0;
#pragma unroll
        for (int e = 0; e < NE; e++) if (e != i1 && l[e] > v2) { v2 = l[e]; i2 = e; }
        float ex = expf(v2 - v1);
        float inv = 1.f / (1.f + ex);
        g_top[2 * token]      = i1;
        g_top[2 * token + 1]  = i2;
        g_gate[2 * token]     = inv;
        g_gate[2 * token + 1] = ex * inv;
    }
}

// ---------------- dispatch scan --------------------------------------------
__global__ void scan_kernel() {
    int e = blockIdx.x;
    __shared__ int wsum[32];
    __shared__ int total_s;
    int lane = threadIdx.x & 31;
    int wid  = threadIdx.x >> 5;
    int running = 0;
    for (int base = 0; base < NTOK; base += 1024) {
        int n = base + threadIdx.x;
        int k = -1;
        int t0 = g_top[2 * n], t1 = g_top[2 * n + 1];
        if (t0 == e) k = 0; else if (t1 == e) k = 1;
        unsigned b = __ballot_sync(0xffffffffu, k >= 0);
        int pw = __popc(b & ((1u << lane) - 1u));
        if (lane == 0) wsum[wid] = __popc(b);
        __syncthreads();
        if (wid == 0) {
            int v = wsum[lane];
            int s = v;
#pragma unroll
            for (int o = 1; o < 32; o <<= 1) {
                int u = __shfl_up_sync(0xffffffffu, s, o);
                if (lane >= o) s += u;
            }
            wsum[lane] = s - v;
            if (lane == 31) total_s = s;
        }
        __syncthreads();
        if (k >= 0) {
            int pos = running + wsum[wid] + pw;
            if (pos < CAP) {
                g_row_token[e * CAP + pos] = n;
                g_row_gate[e * CAP + pos]  = g_gate[2 * n + k];
                g_slot[2 * n + k] = pos;
            } else {
                g_slot[2 * n + k] = -1;
            }
        }
        running += total_s;
        __syncthreads();
    }
    if (threadIdx.x == 0) g_load[e] = running < CAP ? running : CAP;
}

// ---------------- fused persistent GEMM (both layers, work queue) ----------
// items 0..639: gemm1 tiles (H = relu(x@W1^T + b1) as fp16)
// items 640..1279: gemm2 tiles (Oh = gate*(H@W2^T + b2) as fp16), spin on
// per-expert gemm1 completion counters.
__global__ void __launch_bounds__(256)
moe_gemm_fused(const float* __restrict__ b1, const float* __restrict__ b2) {
    extern __shared__ __align__(16) char dsm[];
    __shared__ int sidx;

    const int tid = threadIdx.x;
    const int lane = tid & 31, wid = tid >> 5;
    const int wm = wid >> 1, wn = wid & 1;     // warp tile 64x64
    const uint32_t sb = smem_u32(dsm);
    const uint32_t st0 = sb + 1024;

    // ldmatrix fragment offsets (stage-relative, item-invariant)
    uint32_t aoff[4], boff[4];
#pragma unroll
    for (int ms = 0; ms < 4; ms++)
        aoff[ms] = (uint32_t)(wm * 64 + ms * 16 + (lane & 15)) * PITCH
                 + (uint32_t)(lane >> 4) * 16;
#pragma unroll
    for (int np = 0; np < 4; np++)
        boff[np] = BH_OFF
                 + (uint32_t)(wn * 64 + np * 16 + (lane & 7) + ((lane >> 4) & 1) * 8)
                 * PITCH + (uint32_t)((lane >> 3) & 1) * 16;

    while (true) {
        if (tid == 0) sidx = atomicAdd(&g_next, 1);
        __syncthreads();
        const int idx = sidx;
        __syncthreads();                 // sidx consumed before next overwrite
        if (idx >= TOTAL_ITEMS) return;

        const bool G2 = idx >= G1_ITEMS;
        const int t  = G2 ? idx - G1_ITEMS : idx;
        const int e  = t / TILES_PER_E;
        const int mt = (t % TILES_PER_E) >> 3;
        const int nt = t & 7;
        const int m0 = mt * 256, n0 = nt * 128;
        const int loadE = g_load[e];

        if (G2) {                        // wait for this expert's gemm1 tiles
            if (tid == 0)
                while (ld_acq(&g_done[e]) < TILES_PER_E) __nanosleep(64);
            __syncthreads();
        }

        if (m0 < loadE) {
            // per-thread global source rows
            size_t abase;
            if (G2) abase = ((size_t)e * CAP + m0 + tid) * DIM;
            else {
                int m = m0 + tid;
                abase = (size_t)g_row_token[e * CAP + (m < loadE ? m : loadE - 1)] * DIM;
            }
            const uint16_t* pA = (G2 ? g_Hh : g_xh) + abase;
            const uint16_t* pB = (G2 ? g_w2h : g_w1h)
                               + ((size_t)e * DIM + n0 + (tid & 127)) * DIM;
            const uint32_t dA = (uint32_t)tid * PITCH;
            const uint32_t dB = BH_OFF + (uint32_t)(tid & 127) * PITCH;

            auto issue = [&](int c, uint32_t st) {
                const int k0 = c * BK;
                const uint16_t* sa = pA + k0;
#pragma unroll
                for (int q = 0; q < 8; q++) cpa16(st + dA + q * 16, sa + q * 8);
                if (tid < 128) {
                    const uint16_t* sbp = pB + k0;
#pragma unroll
                    for (int q = 0; q < 8; q++) cpa16(st + dB + q * 16, sbp + q * 8);
                }
            };

            float acc[4][8][4];
#pragma unroll
            for (int i = 0; i < 4; i++)
#pragma unroll
                for (int j = 0; j < 8; j++)
#pragma unroll
                    for (int k = 0; k < 4; k++) acc[i][j][k] = 0.f;

            issue(0, st0);           CP_COMMIT();
            issue(1, st0 + STAGE_B); CP_COMMIT();

            int stg = 0;
#pragma unroll 1
            for (int c = 0; c < NCH; c++) {
                CP_WAIT1();
                __syncthreads();
                const uint32_t st = st0 + (uint32_t)stg * STAGE_B;
#pragma unroll
                for (int s = 0; s < 4; s++) {       // 4 k16-steps per BK=64
                    uint32_t ah[4][4], bh[8][2];
#pragma unroll
                    for (int ms = 0; ms < 4; ms++)
                        ldsm4(ah[ms], st + aoff[ms] + s * 32);
#pragma unroll
                    for (int np = 0; np < 4; np++) {
                        uint32_t tt[4];
                        ldsm4(tt, st + boff[np] + s * 32);
                        bh[2 * np][0] = tt[0]; bh[2 * np][1] = tt[1];
                        bh[2 * np + 1][0] = tt[2]; bh[2 * np + 1][1] = tt[3];
                    }
#pragma unroll
                    for (int ms = 0; ms < 4; ms++)
#pragma unroll
                        for (int ns = 0; ns < 8; ns++)
                            mma_f16(acc[ms][ns], ah[ms], bh[ns]);
                }
                __syncthreads();
                if (c + 2 < NCH) {
                    int nss = stg + 2; if (nss >= 3) nss -= 3;
                    issue(c + 2, st0 + (uint32_t)nss * STAGE_B);
                }
                CP_COMMIT();             // always commit (empty group ok)
                stg = (stg == 2) ? 0 : stg + 1;
            }

            // ---- epilogue ----
            const float* bE = (G2 ? b2 : b1) + e * DIM;
#pragma unroll
            for (int ms = 0; ms < 4; ms++) {
                const int row = m0 + wm * 64 + ms * 16 + (lane >> 2);
                float gr0 = 1.f, gr1 = 1.f;
                if (G2) {
                    gr0 = g_row_gate[e * CAP + row];
                    gr1 = g_row_gate[e * CAP + row + 8];
                }
#pragma unroll
                for (int ns = 0; ns < 8; ns++) {
                    const int col = n0 + wn * 64 + ns * 8 + 2 * (lane & 3);
                    const float2 bv = *(const float2*)(bE + col);
                    float2 v0, v1;
                    v0.x = acc[ms][ns][0] + bv.x; v0.y = acc[ms][ns][1] + bv.y;
                    v1.x = acc[ms][ns][2] + bv.x; v1.y = acc[ms][ns][3] + bv.y;
                    const size_t idx0 = ((size_t)e * CAP + row) * DIM + col;
                    if (G2) {
                        *(uint32_t*)(g_Oh + idx0) = cvt2h(v0.x * gr0, v0.y * gr0);
                        *(uint32_t*)(g_Oh + idx0 + 8 * DIM) = cvt2h(v1.x * gr1, v1.y * gr1);
                    } else {
                        v0.x = v0.x > 0.f ? v0.x : 0.f; v0.y = v0.y > 0.f ? v0.y : 0.f;
                        v1.x = v1.x > 0.f ? v1.x : 0.f; v1.y = v1.y > 0.f ? v1.y : 0.f;
                        *(uint32_t*)(g_Hh + idx0) = cvt2h(v0.x, v0.y);
                        *(uint32_t*)(g_Hh + idx0 + 8 * DIM) = cvt2h(v1.x, v1.y);
                    }
                }
            }
        }

        __syncthreads();                 // all stores done before release
        if (!G2 && tid == 0) {
            __threadfence();
            atomicAdd(&g_done[e], 1);
        }
    }
}

// ---------------- combine: out[t] = sum_k Oh[e_k, slot_k] (gate pre-applied)
__global__ void combine_kernel(float* __restrict__ out) {
    int t = blockIdx.x * 8 + (threadIdx.x >> 5);
    int lane = threadIdx.x & 31;
    float acc[4][8];
#pragma unroll
    for (int i = 0; i < 4; i++)
#pragma unroll
        for (int j = 0; j < 8; j++) acc[i][j] = 0.f;
#pragma unroll
    for (int k = 0; k < 2; k++) {
        int s = g_slot[2 * t + k];
        if (s >= 0) {
            int e = g_top[2 * t + k];
            const uint4* p = (const uint4*)(g_Oh + ((size_t)e * CAP + s) * DIM);
#pragma unroll
            for (int i = 0; i < 4; i++) {
                uint4 v = __ldg(p + lane + i * 32);
                const uint32_t w[4] = {v.x, v.y, v.z, v.w};
#pragma unroll
                for (int j = 0; j < 4; j++) {
                    float2 f = __half22float2(*(const __half2*)&w[j]);
                    acc[i][2 * j]     += f.x;
                    acc[i][2 * j + 1] += f.y;
                }
            }
        }
    }
    float4* o = (float4*)(out + (size_t)t * DIM);
#pragma unroll
    for (int i = 0; i < 4; i++) {
        o[2 * (lane + i * 32)]     = make_float4(acc[i][0], acc[i][1], acc[i][2], acc[i][3]);
        o[2 * (lane + i * 32) + 1] = make_float4(acc[i][4], acc[i][5], acc[i][6], acc[i][7]);
    }
}

// ---------------- stats -----------------------------------------------------
__global__ void stats_kernel(float* __restrict__ out) {
    if (threadIdx.x == 0) {
        float l[NE], s = 0.f;
#pragma unroll
        for (int e = 0; e < NE; e++) { l[e] = (float)g_load[e]; s += l[e]; }
        float inv = 1.f / (s + 1e-8f);
        float loss = 0.f;
#pragma unroll
        for (int e = 0; e < NE; e++) {
            float d = l[e] * inv;
            out[(size_t)NTOK * DIM + 1 + e] = d;
            loss -= d * logf(d + 1e-8f);
        }
        out[(size_t)NTOK * DIM] = loss;
    }
}

// ---------------- launch ----------------------------------------------------
extern "C" void kernel_launch(void* const* d_in, const int* in_sizes, int n_in,
                              void* d_out, int out_size) {
    const float* x  = (const float*)d_in[0];
    const float* Wr = (const float*)d_in[1];
    const float* br = (const float*)d_in[2];
    const float* W1 = (const float*)d_in[3];
    const float* b1 = (const float*)d_in[4];
    const float* W2 = (const float*)d_in[5];
    const float* b2 = (const float*)d_in[6];
    float* out = (float*)d_out;

    cudaFuncSetAttribute(moe_gemm_fused,
                         cudaFuncAttributeMaxDynamicSharedMemorySize, SMEM_DYN);

    uint16_t *w1h, *w2h;
    void *pnext, *pdone;
    cudaGetSymbolAddress((void**)&w1h, g_w1h);
    cudaGetSymbolAddress((void**)&w2h, g_w2h);
    cudaGetSymbolAddress(&pnext, g_next);
    cudaGetSymbolAddress(&pdone, g_done);

    cudaMemsetAsync(pnext, 0, sizeof(int), 0);
    cudaMemsetAsync(pdone, 0, NE * sizeof(int), 0);

    const int wn4 = NE * DIM * DIM / 4;
    cvtw_kernel<<<wn4 / 256, 256>>>((const float4*)W1, (uint2*)w1h, wn4);
    cvtw_kernel<<<wn4 / 256, 256>>>((const float4*)W2, (uint2*)w2h, wn4);

    router_kernel<<<NTOK / 8, 256>>>(x, Wr, br);
    scan_kernel<<<NE, 1024>>>();
    moe_gemm_fused<<<GRID_PERSIST, 256, SMEM_DYN>>>(b1, b2);
    combine_kernel<<<NTOK / 8, 256>>>(out);
    stats_kernel<<<1, 32>>>(out);
}

// round 11
// speedup vs baseline: 2.4647x; 1.0271x over previous
#include <cuda_runtime.h>
#include <cuda_fp16.h>
#include <cstdint>
#include <math.h>

#define NTOK 16384
#define DIM  1024
#define NE   8
#define CAP  2560          // int(1.25 * 16384 / 8)
#define BK   64
#define NCH  (DIM / BK)    // 16
#define PITCH 144          // 64 fp16 = 128B + 16B pad (conflict-free phases)
#define BH_OFF  36864      // 256*144 (A tile)
#define STAGE_B 55296      // A 36864 + B 18432
#define SMEM_DYN (1024 + 3 * STAGE_B)   // 166912
#define TILES_PER_E 80     // 10 m-tiles x 8 n-tiles
#define G1_ITEMS (NE * TILES_PER_E)     // 640
#define TOTAL_ITEMS (2 * G1_ITEMS)      // 1280
#define GRID_PERSIST 152

// ---------------- device scratch (no allocation allowed) -------------------
__device__ int      g_top[NTOK * 2];
__device__ float    g_gate[NTOK * 2];
__device__ int      g_slot[NTOK * 2];
__device__ int      g_row_token[NE * CAP];
__device__ float    g_row_gate[NE * CAP];
__device__ int      g_load[NE];
__device__ int      g_next;                            // work-queue cursor
__device__ int      g_done[NE];                        // gemm1 tiles done / expert
__device__ uint16_t g_xh[(size_t)NTOK * DIM];          // x as fp16
__device__ uint16_t g_w1h[(size_t)NE * DIM * DIM];     // W1 as fp16
__device__ uint16_t g_w2h[(size_t)NE * DIM * DIM];     // W2 as fp16
__device__ uint16_t g_Hh[(size_t)NE * CAP * DIM];      // hidden as fp16
__device__ uint16_t g_Oh[(size_t)NE * CAP * DIM];      // gated expert out, fp16

// ---------------- helpers ---------------------------------------------------
__device__ __forceinline__ uint32_t smem_u32(const void* p) {
    uint32_t a;
    asm("{ .reg .u64 t; cvta.to.shared.u64 t, %1; cvt.u32.u64 %0, t; }"
        : "=r"(a) : "l"(p));
    return a;
}
__device__ __forceinline__ void cpa16(uint32_t dst, const void* src) {
    asm volatile("cp.async.cg.shared.global [%0], [%1], 16;"
                 :: "r"(dst), "l"(src));
}
#define CP_COMMIT() asm volatile("cp.async.commit_group;" ::: "memory")
#define CP_WAIT1()  asm volatile("cp.async.wait_group 1;" ::: "memory")

__device__ __forceinline__ void ldsm4(uint32_t* r, uint32_t addr) {
    asm volatile("ldmatrix.sync.aligned.m8n8.x4.shared.b16 {%0,%1,%2,%3}, [%4];"
                 : "=r"(r[0]), "=r"(r[1]), "=r"(r[2]), "=r"(r[3]) : "r"(addr));
}
__device__ __forceinline__ void mma_f16(float* d, const uint32_t* a,
                                        const uint32_t* b) {
    asm volatile(
        "mma.sync.aligned.m16n8k16.row.col.f32.f16.f16.f32 "
        "{%0,%1,%2,%3}, {%4,%5,%6,%7}, {%8,%9}, {%0,%1,%2,%3};"
        : "+f"(d[0]), "+f"(d[1]), "+f"(d[2]), "+f"(d[3])
        : "r"(a[0]), "r"(a[1]), "r"(a[2]), "r"(a[3]), "r"(b[0]), "r"(b[1]));
}
__device__ __forceinline__ uint32_t cvt2h(float a, float b) {
    __half2 h = __floats2half2_rn(a, b);
    return *(uint32_t*)&h;
}
__device__ __forceinline__ int ld_acq(const int* p) {
    int v;
    asm volatile("ld.acquire.gpu.global.b32 %0, [%1];" : "=r"(v) : "l"(p));
    return v;
}

// ---------------- W convert: fp32 -> fp16 ----------------------------------
__global__ void cvtw_kernel(const float4* __restrict__ src,
                            uint2* __restrict__ dst, int n4) {
    int i = blockIdx.x * blockDim.x + threadIdx.x;
    if (i >= n4) return;
    float4 v = src[i];
    dst[i] = make_uint2(cvt2h(v.x, v.y), cvt2h(v.z, v.w));
}

// ---------------- router + x->fp16 conversion (fused) ----------------------
__global__ void router_kernel(const float* __restrict__ x,
                              const float* __restrict__ Wr,
                              const float* __restrict__ br) {
    int token = (blockIdx.x * blockDim.x + threadIdx.x) >> 5;
    int lane  = threadIdx.x & 31;
    if (token >= NTOK) return;
    const float4* xr = (const float4*)(x + (size_t)token * DIM);
    uint2* xo = (uint2*)(g_xh + (size_t)token * DIM);
    float acc[NE];
#pragma unroll
    for (int e = 0; e < NE; e++) acc[e] = 0.f;
#pragma unroll
    for (int i = 0; i < 8; i++) {
        const int d4 = lane + i * 32;
        float4 v = __ldg(xr + d4);
        xo[d4] = make_uint2(cvt2h(v.x, v.y), cvt2h(v.z, v.w));
#pragma unroll
        for (int e = 0; e < NE; e++) {
            const float4 w = __ldg((const float4*)(Wr + e * DIM) + d4);
            acc[e] += v.x * w.x + v.y * w.y + v.z * w.z + v.w * w.w;
        }
    }
#pragma unroll
    for (int e = 0; e < NE; e++)
#pragma unroll
        for (int o = 16; o; o >>= 1)
            acc[e] += __shfl_xor_sync(0xffffffffu, acc[e], o);
    if (lane == 0) {
        float l[NE];
#pragma unroll
        for (int e = 0; e < NE; e++) l[e] = acc[e] + br[e];
        float v1 = -3.4e38f; int i1 = 0;
#pragma unroll
        for (int e = 0; e < NE; e++) if (l[e] > v1) { v1 = l[e]; i1 = e; }
        float v2 = -3.4e38f; int i2 = 0;
#pragma unroll
        for (int e = 0; e < NE; e++) if (e != i1 && l[e] > v2) { v2 = l[e]; i2 = e; }
        float ex = expf(v2 - v1);
        float inv = 1.f / (1.f + ex);
        g_top[2 * token]      = i1;
        g_top[2 * token + 1]  = i2;
        g_gate[2 * token]     = inv;
        g_gate[2 * token + 1] = ex * inv;
    }
}

// ---------------- dispatch scan --------------------------------------------
__global__ void scan_kernel() {
    int e = blockIdx.x;
    __shared__ int wsum[32];
    __shared__ int total_s;
    int lane = threadIdx.x & 31;
    int wid  = threadIdx.x >> 5;
    int running = 0;
    for (int base = 0; base < NTOK; base += 1024) {
        int n = base + threadIdx.x;
        int k = -1;
        int t0 = g_top[2 * n], t1 = g_top[2 * n + 1];
        if (t0 == e) k = 0; else if (t1 == e) k = 1;
        unsigned b = __ballot_sync(0xffffffffu, k >= 0);
        int pw = __popc(b & ((1u << lane) - 1u));
        if (lane == 0) wsum[wid] = __popc(b);
        __syncthreads();
        if (wid == 0) {
            int v = wsum[lane];
            int s = v;
#pragma unroll
            for (int o = 1; o < 32; o <<= 1) {
                int u = __shfl_up_sync(0xffffffffu, s, o);
                if (lane >= o) s += u;
            }
            wsum[lane] = s - v;
            if (lane == 31) total_s = s;
        }
        __syncthreads();
        if (k >= 0) {
            int pos = running + wsum[wid] + pw;
            if (pos < CAP) {
                g_row_token[e * CAP + pos] = n;
                g_row_gate[e * CAP + pos]  = g_gate[2 * n + k];
                g_slot[2 * n + k] = pos;
            } else {
                g_slot[2 * n + k] = -1;
            }
        }
        running += total_s;
        __syncthreads();
    }
    if (threadIdx.x == 0) g_load[e] = running < CAP ? running : CAP;
}

// ---------------- fused persistent GEMM (both layers, work queue) ----------
// items 0..639: gemm1 tiles (H = relu(x@W1^T + b1) as fp16)
// items 640..1279: gemm2 tiles (Oh = gate*(H@W2^T + b2) as fp16), spin on
// per-expert gemm1 completion counters.
__global__ void __launch_bounds__(256)
moe_gemm_fused(const float* __restrict__ b1, const float* __restrict__ b2) {
    extern __shared__ __align__(16) char dsm[];
    __shared__ int sidx;

    const int tid = threadIdx.x;
    const int lane = tid & 31, wid = tid >> 5;
    const int wm = wid >> 1, wn = wid & 1;     // warp tile 64x64
    const uint32_t sb = smem_u32(dsm);
    const uint32_t st0 = sb + 1024;

    // ldmatrix fragment offsets (stage-relative, item-invariant)
    uint32_t aoff[4], boff[4];
#pragma unroll
    for (int ms = 0; ms < 4; ms++)
        aoff[ms] = (uint32_t)(wm * 64 + ms * 16 + (lane & 15)) * PITCH
                 + (uint32_t)(lane >> 4) * 16;
#pragma unroll
    for (int np = 0; np < 4; np++)
        boff[np] = BH_OFF
                 + (uint32_t)(wn * 64 + np * 16 + (lane & 7) + ((lane >> 4) & 1) * 8)
                 * PITCH + (uint32_t)((lane >> 3) & 1) * 16;

    while (true) {
        if (tid == 0) sidx = atomicAdd(&g_next, 1);
        __syncthreads();
        const int idx = sidx;
        __syncthreads();                 // sidx consumed before next overwrite
        if (idx >= TOTAL_ITEMS) return;

        const bool G2 = idx >= G1_ITEMS;
        const int t  = G2 ? idx - G1_ITEMS : idx;
        const int e  = t / TILES_PER_E;
        const int mt = (t % TILES_PER_E) >> 3;
        const int nt = t & 7;
        const int m0 = mt * 256, n0 = nt * 128;
        const int loadE = g_load[e];

        if (G2) {                        // wait for this expert's gemm1 tiles
            if (tid == 0)
                while (ld_acq(&g_done[e]) < TILES_PER_E) __nanosleep(64);
            __syncthreads();
        }

        if (m0 < loadE) {
            // per-thread global source rows
            size_t abase;
            if (G2) abase = ((size_t)e * CAP + m0 + tid) * DIM;
            else {
                int m = m0 + tid;
                abase = (size_t)g_row_token[e * CAP + (m < loadE ? m : loadE - 1)] * DIM;
            }
            const uint16_t* pA = (G2 ? g_Hh : g_xh) + abase;
            const uint16_t* pB = (G2 ? g_w2h : g_w1h)
                               + ((size_t)e * DIM + n0 + (tid & 127)) * DIM;
            const uint32_t dA = (uint32_t)tid * PITCH;
            const uint32_t dB = BH_OFF + (uint32_t)(tid & 127) * PITCH;

            auto issue = [&](int c, uint32_t st) {
                const int k0 = c * BK;
                const uint16_t* sa = pA + k0;
#pragma unroll
                for (int q = 0; q < 8; q++) cpa16(st + dA + q * 16, sa + q * 8);
                if (tid < 128) {
                    const uint16_t* sbp = pB + k0;
#pragma unroll
                    for (int q = 0; q < 8; q++) cpa16(st + dB + q * 16, sbp + q * 8);
                }
            };

            float acc[4][8][4];
#pragma unroll
            for (int i = 0; i < 4; i++)
#pragma unroll
                for (int j = 0; j < 8; j++)
#pragma unroll
                    for (int k = 0; k < 4; k++) acc[i][j][k] = 0.f;

            issue(0, st0);           CP_COMMIT();
            issue(1, st0 + STAGE_B); CP_COMMIT();

            int stg = 0;
#pragma unroll 1
            for (int c = 0; c < NCH; c++) {
                CP_WAIT1();
                __syncthreads();
                const uint32_t st = st0 + (uint32_t)stg * STAGE_B;
                // frag-double-buffered compute: ldsm(s+1) overlaps MMA(s)
                uint32_t ah[2][16], bh[2][16];
#pragma unroll
                for (int ms = 0; ms < 4; ms++)
                    ldsm4(&ah[0][4 * ms], st + aoff[ms]);
#pragma unroll
                for (int np = 0; np < 4; np++)
                    ldsm4(&bh[0][4 * np], st + boff[np]);
#pragma unroll
                for (int s = 0; s < 4; s++) {       // 4 k16-steps per BK=64
                    const int cur = s & 1, nxt = cur ^ 1;
                    if (s < 3) {
#pragma unroll
                        for (int ms = 0; ms < 4; ms++)
                            ldsm4(&ah[nxt][4 * ms], st + aoff[ms] + (s + 1) * 32);
#pragma unroll
                        for (int np = 0; np < 4; np++)
                            ldsm4(&bh[nxt][4 * np], st + boff[np] + (s + 1) * 32);
                    }
#pragma unroll
                    for (int ms = 0; ms < 4; ms++)
#pragma unroll
                        for (int ns = 0; ns < 8; ns++)
                            mma_f16(acc[ms][ns], &ah[cur][4 * ms], &bh[cur][2 * ns]);
                }
                // single sync per chunk: every warp passed this iteration's
                // top-sync AFTER its compute(c-1), so stage (c+2)%3==(c-1)%3
                // has no remaining readers.
                if (c + 2 < NCH) {
                    int nss = stg + 2; if (nss >= 3) nss -= 3;
                    issue(c + 2, st0 + (uint32_t)nss * STAGE_B);
                }
                CP_COMMIT();             // always commit (empty group ok)
                stg = (stg == 2) ? 0 : stg + 1;
            }

            // ---- epilogue ----
            const float* bE = (G2 ? b2 : b1) + e * DIM;
#pragma unroll
            for (int ms = 0; ms < 4; ms++) {
                const int row = m0 + wm * 64 + ms * 16 + (lane >> 2);
                float gr0 = 1.f, gr1 = 1.f;
                if (G2) {
                    gr0 = g_row_gate[e * CAP + row];
                    gr1 = g_row_gate[e * CAP + row + 8];
                }
#pragma unroll
                for (int ns = 0; ns < 8; ns++) {
                    const int col = n0 + wn * 64 + ns * 8 + 2 * (lane & 3);
                    const float2 bv = *(const float2*)(bE + col);
                    float2 v0, v1;
                    v0.x = acc[ms][ns][0] + bv.x; v0.y = acc[ms][ns][1] + bv.y;
                    v1.x = acc[ms][ns][2] + bv.x; v1.y = acc[ms][ns][3] + bv.y;
                    const size_t idx0 = ((size_t)e * CAP + row) * DIM + col;
                    if (G2) {
                        *(uint32_t*)(g_Oh + idx0) = cvt2h(v0.x * gr0, v0.y * gr0);
                        *(uint32_t*)(g_Oh + idx0 + 8 * DIM) = cvt2h(v1.x * gr1, v1.y * gr1);
                    } else {
                        v0.x = v0.x > 0.f ? v0.x : 0.f; v0.y = v0.y > 0.f ? v0.y : 0.f;
                        v1.x = v1.x > 0.f ? v1.x : 0.f; v1.y = v1.y > 0.f ? v1.y : 0.f;
                        *(uint32_t*)(g_Hh + idx0) = cvt2h(v0.x, v0.y);
                        *(uint32_t*)(g_Hh + idx0 + 8 * DIM) = cvt2h(v1.x, v1.y);
                    }
                }
            }
        }

        __syncthreads();                 // all stores done before release
        if (!G2 && tid == 0) {
            __threadfence();
            atomicAdd(&g_done[e], 1);
        }
    }
}

// ---------------- combine: out[t] = sum_k Oh[e_k, slot_k] (gate pre-applied)
__global__ void combine_kernel(float* __restrict__ out) {
    int t = blockIdx.x * 8 + (threadIdx.x >> 5);
    int lane = threadIdx.x & 31;
    float acc[4][8];
#pragma unroll
    for (int i = 0; i < 4; i++)
#pragma unroll
        for (int j = 0; j < 8; j++) acc[i][j] = 0.f;
#pragma unroll
    for (int k = 0; k < 2; k++) {
        int s = g_slot[2 * t + k];
        if (s >= 0) {
            int e = g_top[2 * t + k];
            const uint4* p = (const uint4*)(g_Oh + ((size_t)e * CAP + s) * DIM);
#pragma unroll
            for (int i = 0; i < 4; i++) {
                uint4 v = __ldg(p + lane + i * 32);
                const uint32_t w[4] = {v.x, v.y, v.z, v.w};
#pragma unroll
                for (int j = 0; j < 4; j++) {
                    float2 f = __half22float2(*(const __half2*)&w[j]);
                    acc[i][2 * j]     += f.x;
                    acc[i][2 * j + 1] += f.y;
                }
            }
        }
    }
    float4* o = (float4*)(out + (size_t)t * DIM);
#pragma unroll
    for (int i = 0; i < 4; i++) {
        o[2 * (lane + i * 32)]     = make_float4(acc[i][0], acc[i][1], acc[i][2], acc[i][3]);
        o[2 * (lane + i * 32) + 1] = make_float4(acc[i][4], acc[i][5], acc[i][6], acc[i][7]);
    }
}

// ---------------- stats -----------------------------------------------------
__global__ void stats_kernel(float* __restrict__ out) {
    if (threadIdx.x == 0) {
        float l[NE], s = 0.f;
#pragma unroll
        for (int e = 0; e < NE; e++) { l[e] = (float)g_load[e]; s += l[e]; }
        float inv = 1.f / (s + 1e-8f);
        float loss = 0.f;
#pragma unroll
        for (int e = 0; e < NE; e++) {
            float d = l[e] * inv;
            out[(size_t)NTOK * DIM + 1 + e] = d;
            loss -= d * logf(d + 1e-8f);
        }
        out[(size_t)NTOK * DIM] = loss;
    }
}

// ---------------- launch ----------------------------------------------------
extern "C" void kernel_launch(void* const* d_in, const int* in_sizes, int n_in,
                              void* d_out, int out_size) {
    const float* x  = (const float*)d_in[0];
    const float* Wr = (const float*)d_in[1];
    const float* br = (const float*)d_in[2];
    const float* W1 = (const float*)d_in[3];
    const float* b1 = (const float*)d_in[4];
    const float* W2 = (const float*)d_in[5];
    const float* b2 = (const float*)d_in[6];
    float* out = (float*)d_out;

    cudaFuncSetAttribute(moe_gemm_fused,
                         cudaFuncAttributeMaxDynamicSharedMemorySize, SMEM_DYN);

    uint16_t *w1h, *w2h;
    void *pnext, *pdone;
    cudaGetSymbolAddress((void**)&w1h, g_w1h);
    cudaGetSymbolAddress((void**)&w2h, g_w2h);
    cudaGetSymbolAddress(&pnext, g_next);
    cudaGetSymbolAddress(&pdone, g_done);

    cudaMemsetAsync(pnext, 0, sizeof(int), 0);
    cudaMemsetAsync(pdone, 0, NE * sizeof(int), 0);

    const int wn4 = NE * DIM * DIM / 4;
    cvtw_kernel<<<wn4 / 256, 256>>>((const float4*)W1, (uint2*)w1h, wn4);
    cvtw_kernel<<<wn4 / 256, 256>>>((const float4*)W2, (uint2*)w2h, wn4);

    router_kernel<<<NTOK / 8, 256>>>(x, Wr, br);
    scan_kernel<<<NE, 1024>>>();
    moe_gemm_fused<<<GRID_PERSIST, 256, SMEM_DYN>>>(b1, b2);
    combine_kernel<<<NTOK / 8, 256>>>(out);
    stats_kernel<<<1, 32>>>(out);
}